// round 1
// baseline (speedup 1.0000x reference)
#include <cuda_runtime.h>

#define BS      16
#define NANCH   33600
#define NCH     56
#define KTOP    3000
#define CAP     4096
#define NB      4096
#define MAXDET  300
#define CONF_T  0.25f
#define IOU_T   0.7f
#define IMGW    1280.0f

// ---------------- static device scratch (no allocations allowed) ----------------
__device__ int    g_cutoff[BS];
__device__ int    g_order [BS * KTOP];   // anchor index per sorted rank
__device__ float  g_score [BS * KTOP];   // masked score per sorted rank
__device__ float4 g_boxes [BS * KTOP];   // xyxy clipped
__device__ int    g_outidx[BS * MAXDET]; // candidate row per output slot, -1 = empty

__device__ __forceinline__ unsigned ordkey(float f) {
    unsigned b = __float_as_uint(f);
    return (b & 0x80000000u) ? ~b : (b | 0x80000000u);
}
__device__ __forceinline__ int bucket_of(float s) {
    int b = (int)(s * 4096.0f);
    return min(4095, max(0, b));
}

// ---------------- K1: per-image score histogram + threshold bucket ----------------
__global__ void k_hist(const float* __restrict__ preds) {
    __shared__ unsigned hist[NB];
    __shared__ int sb;
    const int img = blockIdx.x;
    const int tid = threadIdx.x;
    for (int i = tid; i < NB; i += 1024) hist[i] = 0u;
    if (tid == 0) sb = 0;
    __syncthreads();

    const float* conf = preds + (size_t)img * NCH * NANCH + (size_t)4 * NANCH;
    for (int a = tid; a < NANCH; a += 1024) {
        float s  = conf[a];
        float sp = (s > CONF_T) ? s : -1.0f;
        atomicAdd(&hist[bucket_of(sp)], 1u);
    }
    __syncthreads();

    // suffix-sum scan (Hillis-Steele, two-phase to avoid RAW hazards)
    for (int d = 1; d < NB; d <<= 1) {
        unsigned v[4];
        #pragma unroll
        for (int s = 0; s < 4; s++) {
            int idx = tid + s * 1024;
            v[s] = (idx + d < NB) ? hist[idx + d] : 0u;
        }
        __syncthreads();
        #pragma unroll
        for (int s = 0; s < 4; s++) hist[tid + s * 1024] += v[s];
        __syncthreads();
    }
    // largest bucket b with suffix-count >= KTOP
    #pragma unroll
    for (int s = 0; s < 4; s++) {
        int idx = tid + s * 1024;
        if (hist[idx] >= (unsigned)KTOP) atomicMax(&sb, idx);
    }
    __syncthreads();
    if (tid == 0) g_cutoff[img] = sb;
}

// ---------------- K2: gather candidates + exact bitonic sort (desc) ----------------
__global__ void k_select_sort(const float* __restrict__ preds) {
    __shared__ unsigned long long keys[CAP];
    __shared__ int scnt;
    const int img = blockIdx.x;
    const int tid = threadIdx.x;
    for (int i = tid; i < CAP; i += 1024) keys[i] = 0ull;
    if (tid == 0) scnt = 0;
    const int cutoff = g_cutoff[img];
    __syncthreads();

    const float* conf = preds + (size_t)img * NCH * NANCH + (size_t)4 * NANCH;
    for (int a = tid; a < NANCH; a += 1024) {
        float s  = conf[a];
        float sp = (s > CONF_T) ? s : -1.0f;
        if (bucket_of(sp) >= cutoff) {
            int pos = atomicAdd(&scnt, 1);
            if (pos < CAP) {
                unsigned long long key =
                    ((unsigned long long)ordkey(sp) << 16) | (unsigned)(65535 - a);
                keys[pos] = key;
            }
        }
    }
    __syncthreads();

    // bitonic sort, descending, CAP=4096 elements, 1024 threads x 4
    for (int k = 2; k <= CAP; k <<= 1) {
        for (int j = k >> 1; j > 0; j >>= 1) {
            #pragma unroll
            for (int s = 0; s < 4; s++) {
                int i   = tid + s * 1024;
                int ixj = i ^ j;
                if (ixj > i) {
                    unsigned long long A = keys[i], B = keys[ixj];
                    bool descBlk = ((i & k) == 0);
                    bool sw = descBlk ? (A < B) : (A > B);
                    if (sw) { keys[i] = B; keys[ixj] = A; }
                }
            }
            __syncthreads();
        }
    }

    for (int r = tid; r < KTOP; r += 1024) {
        unsigned long long key = keys[r];
        unsigned u = (unsigned)(key >> 16);
        int   anchor = 0;
        float sc     = -2.0f;    // invalid marker (keep=false)
        if (u != 0u) {
            anchor = 65535 - (int)(key & 0xFFFFull);
            unsigned bits = (u & 0x80000000u) ? (u & 0x7FFFFFFFu) : ~u;
            sc = __uint_as_float(bits);
        }
        g_order[img * KTOP + r] = anchor;
        g_score[img * KTOP + r] = sc;
    }
}

// ---------------- K3: gather boxes, xywh -> xyxy with clipping ----------------
__global__ void k_boxes(const float* __restrict__ preds) {
    int t = blockIdx.x * blockDim.x + threadIdx.x;
    if (t >= BS * KTOP) return;
    int img = t / KTOP;
    int a   = g_order[t];
    const float* base = preds + (size_t)img * NCH * NANCH + a;
    float cx = base[0];
    float cy = base[NANCH];
    float w  = base[2 * (size_t)NANCH];
    float h  = base[3 * (size_t)NANCH];
    float hw = w * 0.5f, hh = h * 0.5f;   // exact (x0.5)
    float4 b;
    b.x = fminf(fmaxf(cx - hw, 0.0f), IMGW);
    b.y = fminf(fmaxf(cy - hh, 0.0f), IMGW);
    b.z = fminf(fmaxf(cx + hw, 0.0f), IMGW);
    b.w = fminf(fmaxf(cy + hh, 0.0f), IMGW);
    g_boxes[t] = b;
}

// ---------------- K4: greedy NMS with early exit at 300 kept ----------------
extern __shared__ char smem_nms[];
__global__ void k_nms() {
    float4*        sbox  = (float4*)smem_nms;                   // 3000 * 16B
    float*         sarea = (float*)(sbox + KTOP);               // 3000 * 4B
    int*           slist = (int*)(sarea + KTOP);                // 300  * 4B
    unsigned char* skeep = (unsigned char*)(slist + MAXDET);    // 3000 * 1B
    __shared__ int scount;
    __shared__ int sdone;

    const int img = blockIdx.x;
    const int tid = threadIdx.x;
    if (tid == 0) { scount = 0; sdone = 0; }

    for (int r = tid; r < KTOP; r += 1024) {
        float4 b = g_boxes[img * KTOP + r];
        sbox[r]  = b;
        sarea[r] = __fmul_rn(b.z - b.x, b.w - b.y);
        skeep[r] = (g_score[img * KTOP + r] > CONF_T) ? 1 : 0;
    }
    __syncthreads();

    float4 rb[3]; float ra[3]; bool ralive[3];
    #pragma unroll
    for (int c = 0; c < 3; c++) {
        int j = tid + c * 1024;
        if (j < KTOP) { rb[c] = sbox[j]; ra[c] = sarea[j]; ralive[c] = (skeep[j] != 0); }
        else ralive[c] = false;
    }

    for (int i = 0; i < KTOP; i++) {
        if (sdone) break;
        if (!skeep[i]) continue;
        float4 bi = sbox[i];
        float  ai = sarea[i];
        #pragma unroll
        for (int c = 0; c < 3; c++) {
            int j = tid + c * 1024;
            if (j > i && ralive[c]) {
                float xx1 = fmaxf(bi.x, rb[c].x);
                float yy1 = fmaxf(bi.y, rb[c].y);
                float xx2 = fminf(bi.z, rb[c].z);
                float yy2 = fminf(bi.w, rb[c].w);
                float ww  = fmaxf(xx2 - xx1, 0.0f);
                float hh  = fmaxf(yy2 - yy1, 0.0f);
                float inter = __fmul_rn(ww, hh);
                if (inter > 0.0f) {
                    // denom = ((ai + aj) - inter) + 1e-9, no FMA contraction
                    float denom = __fadd_rn(__fsub_rn(__fadd_rn(ai, ra[c]), inter), 1e-9f);
                    float iou = inter / denom;   // IEEE div, matches reference rounding
                    if (iou > IOU_T) { ralive[c] = false; skeep[j] = 0; }
                }
            }
        }
        if (tid == 0) {
            slist[scount++] = i;
            if (scount == MAXDET) sdone = 1;
        }
        __syncthreads();
    }
    __syncthreads();
    if (tid < MAXDET)
        g_outidx[img * MAXDET + tid] = (tid < scount) ? slist[tid] : -1;
}

// ---------------- K5: write outputs (ob | osc | okp), zero-fill empties ----------------
__global__ void k_write(const float* __restrict__ preds, float* __restrict__ out) {
    const int img = blockIdx.x;
    const int tid = threadIdx.x;
    const float* pimg = preds + (size_t)img * NCH * NANCH;
    const int OB  = 0;
    const int OSC = BS * MAXDET * 4;
    const int OKP = OSC + BS * MAXDET;

    for (int s = tid; s < MAXDET * 56; s += 1024) {
        int r = s / 56, f = s % 56;
        int q = g_outidx[img * MAXDET + r];
        float v = 0.0f;
        if (q >= 0) {
            if (f < 4) {
                float4 b = g_boxes[img * KTOP + q];
                v = (f == 0) ? b.x : (f == 1) ? b.y : (f == 2) ? b.z : b.w;
            } else if (f == 4) {
                v = g_score[img * KTOP + q];
            } else {
                int c = f - 5;
                int a = g_order[img * KTOP + q];
                v = pimg[(size_t)(5 + c) * NANCH + a];
                if (c < 2) v = fminf(fmaxf(v, 0.0f), IMGW);  // only kpt cols 0,1 clipped
            }
        }
        if (f < 4)       out[OB  + (img * MAXDET + r) * 4 + f] = v;
        else if (f == 4) out[OSC +  img * MAXDET + r] = v;
        else             out[OKP + (img * MAXDET + r) * 51 + (f - 5)] = v;
    }
}

// ---------------- launch ----------------
extern "C" void kernel_launch(void* const* d_in, const int* in_sizes, int n_in,
                              void* d_out, int out_size) {
    const float* preds = (const float*)d_in[0];
    float* out = (float*)d_out;

    // NMS smem: 3000*16 + 3000*4 + 300*4 + 3000 = 64200 bytes
    const int nms_smem = 64256;
    cudaFuncSetAttribute(k_nms, cudaFuncAttributeMaxDynamicSharedMemorySize, nms_smem);

    k_hist<<<BS, 1024>>>(preds);
    k_select_sort<<<BS, 1024>>>(preds);
    int nt = BS * KTOP;
    k_boxes<<<(nt + 255) / 256, 256>>>(preds);
    k_nms<<<BS, 1024, nms_smem>>>();
    k_write<<<BS, 1024>>>(preds, out);
}

// round 2
// speedup vs baseline: 1.1785x; 1.1785x over previous
#include <cuda_runtime.h>

#define BS      16
#define NANCH   33600
#define NCH     56
#define KTOP    3000
#define CAP     4096
#define NB      4096
#define MAXDET  300
#define CONF_T  0.25f
#define IOU_T   0.7f
#define IMGW    1280.0f
#define FULLM   0xFFFFFFFFu

// ---------------- static device scratch ----------------
__device__ int    g_order [BS * KTOP];
__device__ float  g_score [BS * KTOP];
__device__ float4 g_boxes [BS * KTOP];
__device__ int    g_outidx[BS * MAXDET];

__device__ __forceinline__ unsigned ordkey(float f) {
    unsigned b = __float_as_uint(f);
    return (b & 0x80000000u) ? ~b : (b | 0x80000000u);
}
__device__ __forceinline__ int bucket_of(float s) {
    int b = (int)(s * 4096.0f);
    return min(4095, max(0, b));
}

// suppression test, bit-identical to reference rounding (validated rel_err=0 in R1)
__device__ __forceinline__ bool sup_test(float ax, float ay, float az, float aw, float aa,
                                         float bx, float by, float bz, float bw, float ab) {
    float xx1 = fmaxf(ax, bx);
    float yy1 = fmaxf(ay, by);
    float xx2 = fminf(az, bz);
    float yy2 = fminf(aw, bw);
    float ww  = fmaxf(xx2 - xx1, 0.0f);
    float hh  = fmaxf(yy2 - yy1, 0.0f);
    float inter = __fmul_rn(ww, hh);
    if (inter <= 0.0f) return false;
    float denom = __fadd_rn(__fsub_rn(__fadd_rn(aa, ab), inter), 1e-9f);
    return (inter / denom) > IOU_T;
}

// ---------------- K1: fused hist + cutoff + select + bitonic sort + box gather ----------------
__global__ void k_prep(const float* __restrict__ preds) {
    extern __shared__ char sm_prep[];
    unsigned*           hist = (unsigned*)sm_prep;                 // 4096 * 4
    unsigned long long* keys = (unsigned long long*)(sm_prep + NB * 4);  // 4096 * 8
    __shared__ int sb, scnt;

    const int img = blockIdx.x;
    const int tid = threadIdx.x;
    for (int i = tid; i < NB; i += 1024) hist[i] = 0u;
    if (tid == 0) { sb = 0; scnt = 0; }
    __syncthreads();

    const float* conf = preds + (size_t)img * NCH * NANCH + (size_t)4 * NANCH;
    for (int a = tid; a < NANCH; a += 1024) {
        float s  = conf[a];
        float sp = (s > CONF_T) ? s : -1.0f;
        atomicAdd(&hist[bucket_of(sp)], 1u);
    }
    __syncthreads();

    // suffix-sum scan
    for (int d = 1; d < NB; d <<= 1) {
        unsigned v[4];
        #pragma unroll
        for (int s = 0; s < 4; s++) {
            int idx = tid + s * 1024;
            v[s] = (idx + d < NB) ? hist[idx + d] : 0u;
        }
        __syncthreads();
        #pragma unroll
        for (int s = 0; s < 4; s++) hist[tid + s * 1024] += v[s];
        __syncthreads();
    }
    #pragma unroll
    for (int s = 0; s < 4; s++) {
        int idx = tid + s * 1024;
        if (hist[idx] >= (unsigned)KTOP) atomicMax(&sb, idx);
    }
    __syncthreads();
    const int cutoff = sb;

    for (int i = tid; i < CAP; i += 1024) keys[i] = 0ull;
    __syncthreads();
    for (int a = tid; a < NANCH; a += 1024) {
        float s  = conf[a];
        float sp = (s > CONF_T) ? s : -1.0f;
        if (bucket_of(sp) >= cutoff) {
            int pos = atomicAdd(&scnt, 1);
            if (pos < CAP)
                keys[pos] = ((unsigned long long)ordkey(sp) << 16) | (unsigned)(65535 - a);
        }
    }
    __syncthreads();

    // bitonic sort, descending
    for (int k = 2; k <= CAP; k <<= 1) {
        for (int j = k >> 1; j > 0; j >>= 1) {
            #pragma unroll
            for (int s = 0; s < 4; s++) {
                int i   = tid + s * 1024;
                int ixj = i ^ j;
                if (ixj > i) {
                    unsigned long long A = keys[i], B = keys[ixj];
                    bool sw = ((i & k) == 0) ? (A < B) : (A > B);
                    if (sw) { keys[i] = B; keys[ixj] = A; }
                }
            }
            __syncthreads();
        }
    }

    // emit order/score + boxes (xywh -> xyxy, clipped)
    const float* pimg = preds + (size_t)img * NCH * NANCH;
    for (int r = tid; r < KTOP; r += 1024) {
        unsigned long long key = keys[r];
        unsigned u = (unsigned)(key >> 16);
        int   anchor = 0;
        float sc     = -2.0f;
        if (u != 0u) {
            anchor = 65535 - (int)(key & 0xFFFFull);
            unsigned bits = (u & 0x80000000u) ? (u & 0x7FFFFFFFu) : ~u;
            sc = __uint_as_float(bits);
        }
        g_order[img * KTOP + r] = anchor;
        g_score[img * KTOP + r] = sc;
        float cx = pimg[anchor];
        float cy = pimg[(size_t)NANCH + anchor];
        float w  = pimg[2 * (size_t)NANCH + anchor];
        float h  = pimg[3 * (size_t)NANCH + anchor];
        float hw = w * 0.5f, hh = h * 0.5f;
        float4 b;
        b.x = fminf(fmaxf(cx - hw, 0.0f), IMGW);
        b.y = fminf(fmaxf(cy - hh, 0.0f), IMGW);
        b.z = fminf(fmaxf(cx + hw, 0.0f), IMGW);
        b.w = fminf(fmaxf(cy + hh, 0.0f), IMGW);
        g_boxes[img * KTOP + r] = b;
    }
}

// ---------------- K2: tiled warp-cooperative greedy NMS ----------------
__global__ void k_nms() {
    extern __shared__ char sm_nms[];
    float4*        sbox  = (float4*)sm_nms;                   // 3000 * 16
    float*         sarea = (float*)(sbox + KTOP);             // 3000 * 4
    int*           slist = (int*)(sarea + KTOP);              // 300 * 4
    float4*        lbox  = (float4*)(slist + MAXDET);         // 32 * 16
    float*         larea = (float*)(lbox + 32);               // 32 * 4
    unsigned char* skeep = (unsigned char*)(larea + 32);      // 3000
    __shared__ int s_count, s_lcount, s_stop;

    const int img = blockIdx.x;
    const int tid = threadIdx.x;
    if (tid == 0) { s_count = 0; s_stop = 0; }

    for (int r = tid; r < KTOP; r += 1024) {
        float4 b = g_boxes[img * KTOP + r];
        sbox[r]  = b;
        sarea[r] = __fmul_rn(b.z - b.x, b.w - b.y);
        skeep[r] = (g_score[img * KTOP + r] > CONF_T) ? 1 : 0;
    }
    __syncthreads();

    // register-resident candidates (3 per thread)
    float4 rb[3]; float ra[3]; bool ral[3];
    #pragma unroll
    for (int c = 0; c < 3; c++) {
        int j = tid + c * 1024;
        if (j < KTOP) { rb[c] = sbox[j]; ra[c] = sarea[j]; ral[c] = (skeep[j] != 0); }
        else { ral[c] = false; }
    }

    const int lane = tid & 31;
    for (int base = 0; base < KTOP; base += 32) {
        // --- warp 0: intra-tile sequential greedy via shuffles ---
        if (tid < 32) {
            int j = base + lane;
            int alive = (j < KTOP) ? (int)skeep[j] : 0;
            float4 bj = make_float4(0.f, 0.f, 0.f, 0.f);
            float  aj = 0.f;
            if (j < KTOP) { bj = sbox[j]; aj = sarea[j]; }

            for (int i = 0; i < 31; i++) {
                int   ai_alive = __shfl_sync(FULLM, alive, i);
                float bix = __shfl_sync(FULLM, bj.x, i);
                float biy = __shfl_sync(FULLM, bj.y, i);
                float biz = __shfl_sync(FULLM, bj.z, i);
                float biw = __shfl_sync(FULLM, bj.w, i);
                float aia = __shfl_sync(FULLM, aj, i);
                if (ai_alive && lane > i && alive) {
                    if (sup_test(bix, biy, biz, biw, aia, bj.x, bj.y, bj.z, bj.w, aj))
                        alive = 0;
                }
            }
            unsigned m  = __ballot_sync(FULLM, alive);
            int      nk = __popc(m);
            int      old = s_count;           // no writer yet this phase
            if (alive) {
                int pos = __popc(m & ((1u << lane) - 1));
                lbox[pos]  = bj;
                larea[pos] = aj;
                if (old + pos < MAXDET) slist[old + pos] = j;
            }
            if (lane == 0) {
                s_lcount = nk;
                s_count  = old + nk;
                if (old + nk >= MAXDET) s_stop = 1;
            }
        }
        __syncthreads();
        if (s_stop) break;

        // --- all threads: suppress later candidates against kept leaders ---
        const int lc = s_lcount;
        for (int l = 0; l < lc; l++) {
            float4 bl = lbox[l];
            float  al = larea[l];
            #pragma unroll
            for (int c = 0; c < 3; c++) {
                int j = tid + c * 1024;
                if (ral[c] && j >= base + 32) {
                    if (sup_test(bl.x, bl.y, bl.z, bl.w, al,
                                 rb[c].x, rb[c].y, rb[c].z, rb[c].w, ra[c])) {
                        ral[c] = false;
                        skeep[j] = 0;
                    }
                }
            }
        }
        __syncthreads();
    }
    __syncthreads();

    if (tid < MAXDET) {
        int cnt = min(s_count, MAXDET);
        g_outidx[img * MAXDET + tid] = (tid < cnt) ? slist[tid] : -1;
    }
}

// ---------------- K3: write outputs ----------------
__global__ void k_write(const float* __restrict__ preds, float* __restrict__ out) {
    const int img = blockIdx.x;
    const int tid = threadIdx.x;
    const float* pimg = preds + (size_t)img * NCH * NANCH;
    const int OB  = 0;
    const int OSC = BS * MAXDET * 4;
    const int OKP = OSC + BS * MAXDET;

    for (int s = tid; s < MAXDET * 56; s += 1024) {
        int r = s / 56, f = s % 56;
        int q = g_outidx[img * MAXDET + r];
        float v = 0.0f;
        if (q >= 0) {
            if (f < 4) {
                float4 b = g_boxes[img * KTOP + q];
                v = (f == 0) ? b.x : (f == 1) ? b.y : (f == 2) ? b.z : b.w;
            } else if (f == 4) {
                v = g_score[img * KTOP + q];
            } else {
                int c = f - 5;
                int a = g_order[img * KTOP + q];
                v = pimg[(size_t)(5 + c) * NANCH + a];
                if (c < 2) v = fminf(fmaxf(v, 0.0f), IMGW);
            }
        }
        if (f < 4)       out[OB  + (img * MAXDET + r) * 4 + f] = v;
        else if (f == 4) out[OSC +  img * MAXDET + r] = v;
        else             out[OKP + (img * MAXDET + r) * 51 + (f - 5)] = v;
    }
}

// ---------------- launch ----------------
extern "C" void kernel_launch(void* const* d_in, const int* in_sizes, int n_in,
                              void* d_out, int out_size) {
    const float* preds = (const float*)d_in[0];
    float* out = (float*)d_out;

    const int prep_smem = NB * 4 + CAP * 8;                       // 49152
    const int nms_smem  = KTOP * 16 + KTOP * 4 + MAXDET * 4
                        + 32 * 16 + 32 * 4 + KTOP + 64;           // ~64.9KB
    cudaFuncSetAttribute(k_prep, cudaFuncAttributeMaxDynamicSharedMemorySize, prep_smem);
    cudaFuncSetAttribute(k_nms,  cudaFuncAttributeMaxDynamicSharedMemorySize, nms_smem);

    k_prep<<<BS, 1024, prep_smem>>>(preds);
    k_nms <<<BS, 1024, nms_smem>>>();
    k_write<<<BS, 1024>>>(preds, out);
}

// round 3
// speedup vs baseline: 1.3292x; 1.1279x over previous
#include <cuda_runtime.h>

#define BS      16
#define NANCH   33600
#define NCH     56
#define KTOP    3000
#define CAP     4096
#define NB      4096
#define MAXDET  300
#define CONF_T  0.25f
#define IOU_T   0.7f
#define IMGW    1280.0f
#define FULLM   0xFFFFFFFFu
#define NTHR    1024

// ---- smem layout (bytes) ----
// region [0,49152): phase A = hist(16384) + keys(32768); phase B = sbox(48000)
#define OFF_HIST   0
#define OFF_KEYS   16384
#define OFF_SBOX   0
#define OFF_SAREA  49152
#define OFF_SORDER (OFF_SAREA  + 12032)
#define OFF_SSCORE (OFF_SORDER + 12032)
#define OFF_SKEEP  (OFF_SSCORE + 12032)
#define OFF_SLIST  (OFF_SKEEP  + 3008)
#define OFF_LBOX   (OFF_SLIST  + 1216)
#define OFF_LAREA  (OFF_LBOX   + 512)
#define SMEM_TOTAL (OFF_LAREA  + 128)

__device__ __forceinline__ unsigned ordkey(float f) {
    unsigned b = __float_as_uint(f);
    return (b & 0x80000000u) ? ~b : (b | 0x80000000u);
}
__device__ __forceinline__ int bucket_of(float s) {
    int b = (int)(s * 4096.0f);
    return min(4095, max(0, b));
}

// suppression test, bit-identical to reference rounding (rel_err=0 in R1/R2)
__device__ __forceinline__ bool sup_test(float ax, float ay, float az, float aw, float aa,
                                         float bx, float by, float bz, float bw, float ab) {
    float xx1 = fmaxf(ax, bx);
    float yy1 = fmaxf(ay, by);
    float xx2 = fminf(az, bz);
    float yy2 = fminf(aw, bw);
    float ww  = fmaxf(xx2 - xx1, 0.0f);
    float hh  = fmaxf(yy2 - yy1, 0.0f);
    float inter = __fmul_rn(ww, hh);
    if (inter <= 0.0f) return false;
    float denom = __fadd_rn(__fsub_rn(__fadd_rn(aa, ab), inter), 1e-9f);
    return (inter / denom) > IOU_T;
}

// ---- bitonic helpers: element i = 4*tid + s, descending overall ----
__device__ __forceinline__ void cswap(unsigned long long& A, unsigned long long& B, bool desc) {
    unsigned long long mn = (A < B) ? A : B;
    unsigned long long mx = (A < B) ? B : A;
    A = desc ? mx : mn;
    B = desc ? mn : mx;
}
// j in {2,1} in-register steps (valid for k >= 4)
__device__ __forceinline__ void reg_steps(unsigned long long E[4], int k, int tid) {
    bool d = (((4 * tid) & k) == 0);   // uniform across s for k >= 4
    cswap(E[0], E[2], d);
    cswap(E[1], E[3], d);
    cswap(E[0], E[1], d);
    cswap(E[2], E[3], d);
}
// j in {4..64} via warp shuffle
__device__ __forceinline__ void shfl_step(unsigned long long E[4], int j, int k, int tid) {
    int  m       = j >> 2;
    bool upper   = (tid & m) != 0;                // (i & j) != 0
    bool descb   = ((tid & (k >> 2)) == 0);       // (i & k) == 0  (k >= 8)
    bool keepmax = (descb != upper);
    #pragma unroll
    for (int s = 0; s < 4; s++) {
        unsigned long long p = __shfl_xor_sync(FULLM, E[s], m);
        unsigned long long mn = (E[s] < p) ? E[s] : p;
        unsigned long long mx = (E[s] < p) ? p : E[s];
        E[s] = keepmax ? mx : mn;
    }
}
__device__ __forceinline__ void tail64(unsigned long long E[4], int k, int tid) {
    shfl_step(E, 64, k, tid);
    shfl_step(E, 32, k, tid);
    shfl_step(E, 16, k, tid);
    shfl_step(E,  8, k, tid);
    shfl_step(E,  4, k, tid);
    reg_steps(E, k, tid);
}
__device__ __forceinline__ void smem_step(unsigned long long* keys, int j, int k, int tid) {
    #pragma unroll
    for (int s = 0; s < 4; s++) {
        int i   = tid + s * 1024;
        int ixj = i ^ j;
        if (ixj > i) {
            unsigned long long A = keys[i], B = keys[ixj];
            bool sw = (((i & k) == 0)) ? (A < B) : (A > B);
            if (sw) { keys[i] = B; keys[ixj] = A; }
        }
    }
}

// ================= fused kernel: one block per image =================
__global__ void __launch_bounds__(1024) k_fused(const float* __restrict__ preds,
                                                float* __restrict__ out) {
    extern __shared__ char sm[];
    unsigned*           hist  = (unsigned*)(sm + OFF_HIST);
    unsigned long long* keys  = (unsigned long long*)(sm + OFF_KEYS);
    float4*             sbox  = (float4*)(sm + OFF_SBOX);
    float*              sarea = (float*)(sm + OFF_SAREA);
    int*                sorder= (int*)(sm + OFF_SORDER);
    float*              sscore= (float*)(sm + OFF_SSCORE);
    unsigned char*      skeep = (unsigned char*)(sm + OFF_SKEEP);
    int*                slist = (int*)(sm + OFF_SLIST);
    float4*             lbox  = (float4*)(sm + OFF_LBOX);
    float*              larea = (float*)(sm + OFF_LAREA);
    __shared__ int sb, scnt, s_count, s_lcount, s_stop;
    __shared__ unsigned wsum[32];

    const int img  = blockIdx.x;
    const int tid  = threadIdx.x;
    const int lane = tid & 31;
    const int wid  = tid >> 5;
    const float* pimg = preds + (size_t)img * NCH * NANCH;
    const float* conf = pimg + (size_t)4 * NANCH;

    // ---- phase 1: histogram ----
    for (int i = tid; i < NB; i += NTHR) hist[i] = 0u;
    if (tid == 0) { sb = 0; scnt = 0; s_count = 0; s_stop = 0; }
    __syncthreads();
    for (int a = tid; a < NANCH; a += NTHR) {
        float s  = conf[a];
        float sp = (s > CONF_T) ? s : -1.0f;
        atomicAdd(&hist[bucket_of(sp)], 1u);
    }
    __syncthreads();

    // ---- phase 2: hierarchical suffix scan -> cutoff bucket ----
    unsigned h[4], tot = 0;
    #pragma unroll
    for (int s = 0; s < 4; s++) { h[s] = hist[4 * tid + s]; tot += h[s]; }
    unsigned suf = tot;   // inclusive suffix over lanes >= lane (of thread totals)
    #pragma unroll
    for (int d = 1; d < 32; d <<= 1) {
        unsigned v = __shfl_down_sync(FULLM, suf, d);
        if (lane + d < 32) suf += v;
    }
    if (lane == 0) wsum[wid] = suf;
    __syncthreads();
    if (tid < 32) {
        unsigned v  = wsum[tid];
        unsigned sv = v;
        #pragma unroll
        for (int d = 1; d < 32; d <<= 1) {
            unsigned u = __shfl_down_sync(FULLM, sv, d);
            if (tid + d < 32) sv += u;
        }
        wsum[tid] = sv - v;   // exclusive suffix over warps > tid
    }
    __syncthreads();
    {
        unsigned run = wsum[wid] + (suf - tot);  // sum over all threads with larger tid
        #pragma unroll
        for (int s = 3; s >= 0; s--) {
            run += h[s];
            if (run >= (unsigned)KTOP) { atomicMax(&sb, 4 * tid + s); break; }
        }
    }
    __syncthreads();
    const int cutoff = sb;

    // ---- phase 3: select candidates ----
    for (int i = tid; i < CAP; i += NTHR) keys[i] = 0ull;
    __syncthreads();
    for (int a = tid; a < NANCH; a += NTHR) {
        float s  = conf[a];
        float sp = (s > CONF_T) ? s : -1.0f;
        if (bucket_of(sp) >= cutoff) {
            int pos = atomicAdd(&scnt, 1);
            if (pos < CAP)
                keys[pos] = ((unsigned long long)ordkey(sp) << 16) | (unsigned)(65535 - a);
        }
    }
    __syncthreads();

    // ---- phase 4: hybrid bitonic sort (descending), 4096 keys ----
    unsigned long long E[4];
    #pragma unroll
    for (int s = 0; s < 4; s++) E[s] = keys[4 * tid + s];

    // k = 2
    cswap(E[0], E[1], true);
    cswap(E[2], E[3], false);
    // k = 4
    reg_steps(E, 4, tid);
    // k = 8..64
    shfl_step(E, 4, 8, tid);   reg_steps(E, 8, tid);
    shfl_step(E, 8, 16, tid);  shfl_step(E, 4, 16, tid);  reg_steps(E, 16, tid);
    shfl_step(E, 16, 32, tid); shfl_step(E, 8, 32, tid);  shfl_step(E, 4, 32, tid); reg_steps(E, 32, tid);
    shfl_step(E, 32, 64, tid); shfl_step(E, 16, 64, tid); shfl_step(E, 8, 64, tid);
    shfl_step(E, 4, 64, tid);  reg_steps(E, 64, tid);
    // k = 128
    tail64(E, 128, tid);
    // k = 256..4096 (smem for j >= 128, then reg/shfl tail)
    for (int k = 256; k <= CAP; k <<= 1) {
        __syncthreads();
        #pragma unroll
        for (int s = 0; s < 4; s++) keys[4 * tid + s] = E[s];
        __syncthreads();
        for (int j = k >> 1; j >= 128; j >>= 1) {
            smem_step(keys, j, k, tid);
            __syncthreads();
        }
        #pragma unroll
        for (int s = 0; s < 4; s++) E[s] = keys[4 * tid + s];
        tail64(E, k, tid);
    }
    __syncthreads();   // everyone has final regs; keys region may now be recycled

    // ---- phase 5: decode + box gather (sbox overwrites hist/keys region) ----
    #pragma unroll
    for (int s = 0; s < 4; s++) {
        int r = 4 * tid + s;
        if (r < KTOP) {
            unsigned u = (unsigned)(E[s] >> 16);
            int   anchor = 0;
            float sc     = -2.0f;
            if (u != 0u) {
                anchor = 65535 - (int)(E[s] & 0xFFFFull);
                unsigned bits = (u & 0x80000000u) ? (u & 0x7FFFFFFFu) : ~u;
                sc = __uint_as_float(bits);
            }
            float cx = pimg[anchor];
            float cy = pimg[(size_t)NANCH + anchor];
            float w  = pimg[2 * (size_t)NANCH + anchor];
            float ht = pimg[3 * (size_t)NANCH + anchor];
            float hw = w * 0.5f, hh = ht * 0.5f;
            float4 b;
            b.x = fminf(fmaxf(cx - hw, 0.0f), IMGW);
            b.y = fminf(fmaxf(cy - hh, 0.0f), IMGW);
            b.z = fminf(fmaxf(cx + hw, 0.0f), IMGW);
            b.w = fminf(fmaxf(cy + hh, 0.0f), IMGW);
            sbox[r]   = b;
            sarea[r]  = __fmul_rn(b.z - b.x, b.w - b.y);
            skeep[r]  = (sc > CONF_T) ? 1 : 0;
            sorder[r] = anchor;
            sscore[r] = sc;
        }
    }
    __syncthreads();

    // ---- phase 6: tiled warp-cooperative greedy NMS ----
    float4 rb[3]; float ra[3]; bool ral[3];
    #pragma unroll
    for (int c = 0; c < 3; c++) {
        int j = tid + c * 1024;
        if (j < KTOP) { rb[c] = sbox[j]; ra[c] = sarea[j]; ral[c] = (skeep[j] != 0); }
        else { ral[c] = false; }
    }

    for (int base = 0; base < KTOP; base += 32) {
        if (tid < 32) {
            int j = base + lane;
            int alive = (j < KTOP) ? (int)skeep[j] : 0;
            float4 bj = make_float4(0.f, 0.f, 0.f, 0.f);
            float  aj = 0.f;
            if (j < KTOP) { bj = sbox[j]; aj = sarea[j]; }

            for (int i = 0; i < 31; i++) {
                int   ia  = __shfl_sync(FULLM, alive, i);
                float bix = __shfl_sync(FULLM, bj.x, i);
                float biy = __shfl_sync(FULLM, bj.y, i);
                float biz = __shfl_sync(FULLM, bj.z, i);
                float biw = __shfl_sync(FULLM, bj.w, i);
                float aia = __shfl_sync(FULLM, aj, i);
                if (ia && lane > i && alive) {
                    if (sup_test(bix, biy, biz, biw, aia, bj.x, bj.y, bj.z, bj.w, aj))
                        alive = 0;
                }
            }
            unsigned m   = __ballot_sync(FULLM, alive);
            int      nk  = __popc(m);
            int      old = s_count;
            if (alive) {
                int pos = __popc(m & ((1u << lane) - 1));
                lbox[pos]  = bj;
                larea[pos] = aj;
                if (old + pos < MAXDET) slist[old + pos] = j;
            }
            if (lane == 0) {
                s_lcount = nk;
                s_count  = old + nk;
                if (old + nk >= MAXDET) s_stop = 1;
            }
        }
        __syncthreads();
        if (s_stop) break;

        const int lc = s_lcount;
        for (int l = 0; l < lc; l++) {
            float4 bl = lbox[l];
            float  al = larea[l];
            #pragma unroll
            for (int c = 0; c < 3; c++) {
                int j = tid + c * 1024;
                if (ral[c] && j >= base + 32) {
                    if (sup_test(bl.x, bl.y, bl.z, bl.w, al,
                                 rb[c].x, rb[c].y, rb[c].z, rb[c].w, ra[c])) {
                        ral[c]   = false;
                        skeep[j] = 0;
                    }
                }
            }
        }
        __syncthreads();
    }
    __syncthreads();

    // ---- phase 7: write outputs ----
    const int cnt = min(s_count, MAXDET);
    const int OB  = 0;
    const int OSC = BS * MAXDET * 4;
    const int OKP = OSC + BS * MAXDET;
    for (int s = tid; s < MAXDET * 56; s += NTHR) {
        int r = s / 56, f = s % 56;
        int q = (r < cnt) ? slist[r] : -1;
        float v = 0.0f;
        if (q >= 0) {
            if (f < 4) {
                float4 b = sbox[q];
                v = (f == 0) ? b.x : (f == 1) ? b.y : (f == 2) ? b.z : b.w;
            } else if (f == 4) {
                v = sscore[q];
            } else {
                int c = f - 5;
                int a = sorder[q];
                v = pimg[(size_t)(5 + c) * NANCH + a];
                if (c < 2) v = fminf(fmaxf(v, 0.0f), IMGW);
            }
        }
        if (f < 4)       out[OB  + (img * MAXDET + r) * 4 + f] = v;
        else if (f == 4) out[OSC +  img * MAXDET + r] = v;
        else             out[OKP + (img * MAXDET + r) * 51 + (f - 5)] = v;
    }
}

// ---------------- launch ----------------
extern "C" void kernel_launch(void* const* d_in, const int* in_sizes, int n_in,
                              void* d_out, int out_size) {
    const float* preds = (const float*)d_in[0];
    float* out = (float*)d_out;
    cudaFuncSetAttribute(k_fused, cudaFuncAttributeMaxDynamicSharedMemorySize, SMEM_TOTAL);
    k_fused<<<BS, NTHR, SMEM_TOTAL>>>(preds, out);
}

// round 4
// speedup vs baseline: 3.6898x; 2.7760x over previous
#include <cuda_runtime.h>

#define BS      16
#define NANCH   33600
#define NCH     56
#define KTOP    3000
#define CAP     4096
#define NB      4096
#define MAXDET  300
#define CONF_T  0.25f
#define IOU_T   0.7f
#define IMGW    1280.0f
#define FULLM   0xFFFFFFFFu
#define NTHR    1024

// ---- smem layout (bytes) ----
// region [0,49152): phase A = hist(16384)+keys(32768); phase B = sbox(48128)
#define OFF_HIST   0
#define OFF_KEYS   16384
#define OFF_SBOX   0
#define OFF_SAREA  49152
#define OFF_SORDER (OFF_SAREA  + 12032)
#define OFF_SSCORE (OFF_SORDER + 12032)
#define OFF_SLIST  (OFF_SSCORE + 12032)
#define OFF_LBOX   (OFF_SLIST  + 1344)
#define OFF_LAREA  (OFF_LBOX   + 5376)
#define OFF_SROW   (OFF_LAREA  + 1344)
#define OFF_SSUP   (OFF_SROW   + 128)
#define SMEM_TOTAL (OFF_SSUP   + 64)

__device__ __forceinline__ unsigned ordkey(float f) {
    unsigned b = __float_as_uint(f);
    return (b & 0x80000000u) ? ~b : (b | 0x80000000u);
}
__device__ __forceinline__ int bucket_of(float s) {
    int b = (int)(s * 4096.0f);
    return min(4095, max(0, b));
}

// suppression test, bit-identical to reference rounding (rel_err=0 R1..R3)
__device__ __forceinline__ bool sup_test(float ax, float ay, float az, float aw, float aa,
                                         float bx, float by, float bz, float bw, float ab) {
    float xx1 = fmaxf(ax, bx);
    float yy1 = fmaxf(ay, by);
    float xx2 = fminf(az, bz);
    float yy2 = fminf(aw, bw);
    float ww  = fmaxf(xx2 - xx1, 0.0f);
    float hh  = fmaxf(yy2 - yy1, 0.0f);
    float inter = __fmul_rn(ww, hh);
    if (inter <= 0.0f) return false;
    float denom = __fadd_rn(__fsub_rn(__fadd_rn(aa, ab), inter), 1e-9f);
    return (inter / denom) > IOU_T;
}

// ---- bitonic helpers: element i = 4*tid + s, descending overall ----
__device__ __forceinline__ void cswap(unsigned long long& A, unsigned long long& B, bool desc) {
    unsigned long long mn = (A < B) ? A : B;
    unsigned long long mx = (A < B) ? B : A;
    A = desc ? mx : mn;
    B = desc ? mn : mx;
}
__device__ __forceinline__ void reg_steps(unsigned long long E[4], int k, int tid) {
    bool d = (((4 * tid) & k) == 0);
    cswap(E[0], E[2], d);
    cswap(E[1], E[3], d);
    cswap(E[0], E[1], d);
    cswap(E[2], E[3], d);
}
__device__ __forceinline__ void shfl_step(unsigned long long E[4], int j, int k, int tid) {
    int  m       = j >> 2;
    bool upper   = (tid & m) != 0;
    bool descb   = ((tid & (k >> 2)) == 0);
    bool keepmax = (descb != upper);
    #pragma unroll
    for (int s = 0; s < 4; s++) {
        unsigned long long p = __shfl_xor_sync(FULLM, E[s], m);
        unsigned long long mn = (E[s] < p) ? E[s] : p;
        unsigned long long mx = (E[s] < p) ? p : E[s];
        E[s] = keepmax ? mx : mn;
    }
}
__device__ __forceinline__ void tail64(unsigned long long E[4], int k, int tid) {
    shfl_step(E, 64, k, tid);
    shfl_step(E, 32, k, tid);
    shfl_step(E, 16, k, tid);
    shfl_step(E,  8, k, tid);
    shfl_step(E,  4, k, tid);
    reg_steps(E, k, tid);
}
__device__ __forceinline__ void smem_step(unsigned long long* keys, int j, int k, int tid) {
    #pragma unroll
    for (int s = 0; s < 4; s++) {
        int i   = tid + s * 1024;
        int ixj = i ^ j;
        if (ixj > i) {
            unsigned long long A = keys[i], B = keys[ixj];
            bool sw = (((i & k) == 0)) ? (A < B) : (A > B);
            if (sw) { keys[i] = B; keys[ixj] = A; }
        }
    }
}

// ================= fused kernel: one block per image =================
__global__ void __launch_bounds__(1024) k_fused(const float* __restrict__ preds,
                                                float* __restrict__ out) {
    extern __shared__ char sm[];
    unsigned*           hist  = (unsigned*)(sm + OFF_HIST);
    unsigned long long* keys  = (unsigned long long*)(sm + OFF_KEYS);
    float4*             sbox  = (float4*)(sm + OFF_SBOX);
    float*              sarea = (float*)(sm + OFF_SAREA);
    int*                sorder= (int*)(sm + OFF_SORDER);
    float*              sscore= (float*)(sm + OFF_SSCORE);
    int*                slist = (int*)(sm + OFF_SLIST);     // 336
    float4*             lbox  = (float4*)(sm + OFF_LBOX);   // 336
    float*              larea = (float*)(sm + OFF_LAREA);   // 336
    unsigned*           srow  = (unsigned*)(sm + OFF_SROW); // 32
    unsigned char*      ssup  = (unsigned char*)(sm + OFF_SSUP); // 32
    __shared__ int sb, scnt, s_count, s_stop;
    __shared__ unsigned wsum[32];

    const int img  = blockIdx.x;
    const int tid  = threadIdx.x;
    const int lane = tid & 31;
    const int wid  = tid >> 5;
    const float* pimg = preds + (size_t)img * NCH * NANCH;
    const float* conf = pimg + (size_t)4 * NANCH;

    // ---- phase 1: histogram (above-threshold scores only) ----
    for (int i = tid; i < NB; i += NTHR) hist[i] = 0u;
    if (tid == 0) { sb = 0; scnt = 0; s_count = 0; s_stop = 0; }
    __syncthreads();
    for (int a = tid; a < NANCH; a += NTHR) {
        float s = conf[a];
        if (s > CONF_T) atomicAdd(&hist[bucket_of(s)], 1u);
    }
    __syncthreads();

    // ---- phase 2: hierarchical suffix scan -> cutoff bucket ----
    unsigned h[4], tot = 0;
    #pragma unroll
    for (int s = 0; s < 4; s++) { h[s] = hist[4 * tid + s]; tot += h[s]; }
    unsigned suf = tot;
    #pragma unroll
    for (int d = 1; d < 32; d <<= 1) {
        unsigned v = __shfl_down_sync(FULLM, suf, d);
        if (lane + d < 32) suf += v;
    }
    if (lane == 0) wsum[wid] = suf;
    __syncthreads();
    if (tid < 32) {
        unsigned v  = wsum[tid];
        unsigned sv = v;
        #pragma unroll
        for (int d = 1; d < 32; d <<= 1) {
            unsigned u = __shfl_down_sync(FULLM, sv, d);
            if (tid + d < 32) sv += u;
        }
        wsum[tid] = sv - v;
    }
    __syncthreads();
    {
        unsigned run = wsum[wid] + (suf - tot);
        #pragma unroll
        for (int s = 3; s >= 0; s--) {
            run += h[s];
            if (run >= (unsigned)KTOP) { atomicMax(&sb, 4 * tid + s); break; }
        }
    }
    __syncthreads();
    const int cutoff = sb;

    // ---- phase 3: select candidates ----
    for (int i = tid; i < CAP; i += NTHR) keys[i] = 0ull;
    __syncthreads();
    for (int a = tid; a < NANCH; a += NTHR) {
        float s = conf[a];
        if (s > CONF_T && bucket_of(s) >= cutoff) {
            int pos = atomicAdd(&scnt, 1);
            if (pos < CAP)
                keys[pos] = ((unsigned long long)ordkey(s) << 16) | (unsigned)(65535 - a);
        }
    }
    __syncthreads();

    // ---- phase 4: hybrid bitonic sort (descending), 4096 keys ----
    unsigned long long E[4];
    #pragma unroll
    for (int s = 0; s < 4; s++) E[s] = keys[4 * tid + s];

    cswap(E[0], E[1], true);
    cswap(E[2], E[3], false);
    reg_steps(E, 4, tid);
    shfl_step(E, 4, 8, tid);   reg_steps(E, 8, tid);
    shfl_step(E, 8, 16, tid);  shfl_step(E, 4, 16, tid);  reg_steps(E, 16, tid);
    shfl_step(E, 16, 32, tid); shfl_step(E, 8, 32, tid);  shfl_step(E, 4, 32, tid); reg_steps(E, 32, tid);
    shfl_step(E, 32, 64, tid); shfl_step(E, 16, 64, tid); shfl_step(E, 8, 64, tid);
    shfl_step(E, 4, 64, tid);  reg_steps(E, 64, tid);
    tail64(E, 128, tid);
    for (int k = 256; k <= CAP; k <<= 1) {
        __syncthreads();
        #pragma unroll
        for (int s = 0; s < 4; s++) keys[4 * tid + s] = E[s];
        __syncthreads();
        for (int j = k >> 1; j >= 128; j >>= 1) {
            smem_step(keys, j, k, tid);
            __syncthreads();
        }
        #pragma unroll
        for (int s = 0; s < 4; s++) E[s] = keys[4 * tid + s];
        tail64(E, k, tid);
    }
    __syncthreads();   // keys region now dead, recycle as sbox

    // ---- phase 5: decode + box gather ----
    #pragma unroll
    for (int s = 0; s < 4; s++) {
        int r = 4 * tid + s;
        if (r < KTOP) {
            unsigned u = (unsigned)(E[s] >> 16);
            int   anchor = 0;
            float sc     = -2.0f;
            if (u != 0u) {
                anchor = 65535 - (int)(E[s] & 0xFFFFull);
                unsigned bits = (u & 0x80000000u) ? (u & 0x7FFFFFFFu) : ~u;
                sc = __uint_as_float(bits);
            }
            float cx = pimg[anchor];
            float cy = pimg[(size_t)NANCH + anchor];
            float w  = pimg[2 * (size_t)NANCH + anchor];
            float ht = pimg[3 * (size_t)NANCH + anchor];
            float hw = w * 0.5f, hh = ht * 0.5f;
            float4 b;
            b.x = fminf(fmaxf(cx - hw, 0.0f), IMGW);
            b.y = fminf(fmaxf(cy - hh, 0.0f), IMGW);
            b.z = fminf(fmaxf(cx + hw, 0.0f), IMGW);
            b.w = fminf(fmaxf(cy + hh, 0.0f), IMGW);
            sbox[r]   = b;
            sarea[r]  = __fmul_rn(b.z - b.x, b.w - b.y);
            sorder[r] = anchor;
            sscore[r] = sc;
        }
    }
    if (tid < 32) ssup[tid] = 0;
    __syncthreads();

    // ---- phase 6: greedy NMS, new-tile-vs-kept-list dataflow ----
    // thread = (row i = tid>>5, candidate j = tid&31)
    const int irow = wid;   // 0..31
    const int jcol = lane;  // 0..31
    for (int base = 0; base < KTOP; base += 32) {
        // Phase A (all threads): leader tests + intra-tile pair test
        int cj  = base + jcol;
        int cjc = min(cj, KTOP - 1);
        bool aj_valid = (cj < KTOP) && (sscore[cjc] > CONF_T);
        float4 bj = sbox[cjc];
        float  aj = sarea[cjc];

        bool sup = false;
        if (aj_valid) {
            const int cnt = s_count;
            for (int l = irow; l < cnt; l += 32) {
                float4 bl = lbox[l];
                if (sup_test(bl.x, bl.y, bl.z, bl.w, larea[l],
                             bj.x, bj.y, bj.z, bj.w, aj)) { sup = true; break; }
            }
        }
        bool pair = false;
        if (irow < jcol) {   // geometric test only; aliveness applied in resolve
            float4 bi = sbox[base + irow];
            float  ai = sarea[base + irow];
            pair = sup_test(bi.x, bi.y, bi.z, bi.w, ai,
                            bj.x, bj.y, bj.z, bj.w, aj);
        }
        unsigned rowm = __ballot_sync(FULLM, pair);  // warp=row i, lanes=j
        if (jcol == 0) srow[irow] = rowm;
        if (sup) ssup[jcol] = 1;   // benign byte-store race
        __syncthreads();

        // Phase B (warp 0): resolve intra-tile greedy + append leaders
        if (tid < 32) {
            int  j2  = lane;
            int  c2  = base + j2;
            bool alive = (c2 < KTOP) && (sscore[min(c2, KTOP-1)] > CONF_T) && (ssup[j2] == 0);
            unsigned initb = __ballot_sync(FULLM, alive);
            unsigned rm    = srow[lane];
            unsigned kept;
            if (__ballot_sync(FULLM, (rm & initb) != 0) == 0u) {
                kept = initb;    // no geometric intra-tile suppression among alive
            } else {
                unsigned S = 0; kept = 0;
                #pragma unroll 4
                for (int ii = 0; ii < 32; ii++) {
                    unsigned ri = __shfl_sync(FULLM, rm, ii);
                    bool ki = ((initb >> ii) & 1u) && !((S >> ii) & 1u);
                    if (ki) { kept |= (1u << ii); S |= ri; }
                }
            }
            int nk  = __popc(kept);
            int old = s_count;
            if ((kept >> lane) & 1u) {
                int pos = old + __popc(kept & ((1u << lane) - 1u));
                lbox[pos]  = sbox[c2];
                larea[pos] = sarea[c2];
                if (pos < MAXDET) slist[pos] = c2;
            }
            ssup[lane] = 0;   // reset for next tile
            if (lane == 0) {
                s_count = old + nk;
                if (old + nk >= MAXDET) s_stop = 1;
            }
        }
        __syncthreads();
        if (s_stop) break;
    }
    __syncthreads();

    // ---- phase 7: write outputs ----
    const int cnt = min(s_count, MAXDET);
    const int OB  = 0;
    const int OSC = BS * MAXDET * 4;
    const int OKP = OSC + BS * MAXDET;
    for (int s = tid; s < MAXDET * 56; s += NTHR) {
        int r = s / 56, f = s % 56;
        int q = (r < cnt) ? slist[r] : -1;
        float v = 0.0f;
        if (q >= 0) {
            if (f < 4) {
                float4 b = sbox[q];
                v = (f == 0) ? b.x : (f == 1) ? b.y : (f == 2) ? b.z : b.w;
            } else if (f == 4) {
                v = sscore[q];
            } else {
                int c = f - 5;
                int a = sorder[q];
                v = pimg[(size_t)(5 + c) * NANCH + a];
                if (c < 2) v = fminf(fmaxf(v, 0.0f), IMGW);
            }
        }
        if (f < 4)       out[OB  + (img * MAXDET + r) * 4 + f] = v;
        else if (f == 4) out[OSC +  img * MAXDET + r] = v;
        else             out[OKP + (img * MAXDET + r) * 51 + (f - 5)] = v;
    }
}

// ---------------- launch ----------------
extern "C" void kernel_launch(void* const* d_in, const int* in_sizes, int n_in,
                              void* d_out, int out_size) {
    const float* preds = (const float*)d_in[0];
    float* out = (float*)d_out;
    cudaFuncSetAttribute(k_fused, cudaFuncAttributeMaxDynamicSharedMemorySize, SMEM_TOTAL);
    k_fused<<<BS, NTHR, SMEM_TOTAL>>>(preds, out);
}

// round 5
// speedup vs baseline: 4.9803x; 1.3498x over previous
#include <cuda_runtime.h>

#define BS      16
#define NANCH   33600
#define NV4     (NANCH / 4)
#define NCH     56
#define KTOP    3000
#define CAP     4096
#define NB      4096
#define MAXDET  300
#define CONF_T  0.25f
#define IOU_T   0.7f
#define IMGW    1280.0f
#define FULLM   0xFFFFFFFFu
#define NTHR    1024

// ---- smem layout (bytes), no phase overlap ----
#define OFF_HIST   0                        // 4096*4  = 16384
#define OFF_BSTART 16384                    // 4096*4  = 16384
#define OFF_KEYS   32768                    // 4096*8  = 32768
#define OFF_KEYS2  65536                    // 4096*8  = 32768
#define OFF_SBOX   98304                    // 3008*16 = 48128
#define OFF_SAREA  (OFF_SBOX   + 48128)     // 3008*4  = 12032
#define OFF_SORDER (OFF_SAREA  + 12032)
#define OFF_SSCORE (OFF_SORDER + 12032)
#define OFF_SLIST  (OFF_SSCORE + 12032)     // 336*4   = 1344
#define OFF_LBOX   (OFF_SLIST  + 1344)      // 336*16  = 5376
#define OFF_LAREA  (OFF_LBOX   + 5376)      // 336*4   = 1344
#define OFF_SROW   (OFF_LAREA  + 1344)      // 32*4    = 128
#define OFF_SSUP   (OFF_SROW   + 128)       // 32 + pad
#define SMEM_TOTAL (OFF_SSUP   + 64)        // 190784

__device__ __forceinline__ unsigned ordkey(float f) {
    unsigned b = __float_as_uint(f);
    return (b & 0x80000000u) ? ~b : (b | 0x80000000u);
}
__device__ __forceinline__ float inv_ordkey(unsigned u) {
    unsigned bits = (u & 0x80000000u) ? (u & 0x7FFFFFFFu) : ~u;
    return __uint_as_float(bits);
}
__device__ __forceinline__ int bucket_of(float s) {
    int b = (int)(s * 4096.0f);
    return min(4095, max(0, b));
}

// suppression test, bit-identical to reference rounding (rel_err=0 R1..R4)
__device__ __forceinline__ bool sup_test(float ax, float ay, float az, float aw, float aa,
                                         float bx, float by, float bz, float bw, float ab) {
    float xx1 = fmaxf(ax, bx);
    float yy1 = fmaxf(ay, by);
    float xx2 = fminf(az, bz);
    float yy2 = fminf(aw, bw);
    float ww  = fmaxf(xx2 - xx1, 0.0f);
    float hh  = fmaxf(yy2 - yy1, 0.0f);
    float inter = __fmul_rn(ww, hh);
    if (inter <= 0.0f) return false;
    float denom = __fadd_rn(__fsub_rn(__fadd_rn(aa, ab), inter), 1e-9f);
    return (inter / denom) > IOU_T;
}

// ================= fused kernel: one block per image =================
__global__ void __launch_bounds__(1024) k_fused(const float* __restrict__ preds,
                                                float* __restrict__ out) {
    extern __shared__ char sm[];
    unsigned*           hist  = (unsigned*)(sm + OFF_HIST);
    unsigned*           bstart= (unsigned*)(sm + OFF_BSTART);
    unsigned long long* keys  = (unsigned long long*)(sm + OFF_KEYS);
    unsigned long long* keys2 = (unsigned long long*)(sm + OFF_KEYS2);
    float4*             sbox  = (float4*)(sm + OFF_SBOX);
    float*              sarea = (float*)(sm + OFF_SAREA);
    int*                sorder= (int*)(sm + OFF_SORDER);
    float*              sscore= (float*)(sm + OFF_SSCORE);
    int*                slist = (int*)(sm + OFF_SLIST);
    float4*             lbox  = (float4*)(sm + OFF_LBOX);
    float*              larea = (float*)(sm + OFF_LAREA);
    unsigned*           srow  = (unsigned*)(sm + OFF_SROW);
    unsigned char*      ssup  = (unsigned char*)(sm + OFF_SSUP);
    __shared__ int sb, s_count, s_stop;
    __shared__ unsigned wsum[32];

    const int img  = blockIdx.x;
    const int tid  = threadIdx.x;
    const int lane = tid & 31;
    const int wid  = tid >> 5;
    const float* pimg = preds + (size_t)img * NCH * NANCH;
    const float4* conf4 = (const float4*)(pimg + (size_t)4 * NANCH);

    // ---- phase 1: histogram (above-threshold only), float4 reads ----
    for (int i = tid; i < NB; i += NTHR) hist[i] = 0u;
    if (tid == 0) { sb = 0; s_count = 0; s_stop = 0; }
    __syncthreads();
    for (int i = tid; i < NV4; i += NTHR) {
        float4 v = conf4[i];
        if (v.x > CONF_T) atomicAdd(&hist[bucket_of(v.x)], 1u);
        if (v.y > CONF_T) atomicAdd(&hist[bucket_of(v.y)], 1u);
        if (v.z > CONF_T) atomicAdd(&hist[bucket_of(v.z)], 1u);
        if (v.w > CONF_T) atomicAdd(&hist[bucket_of(v.w)], 1u);
    }
    __syncthreads();

    // ---- phase 2: suffix scan -> per-bucket start offsets + cutoff ----
    uint4 hv = ((const uint4*)hist)[tid];
    unsigned tot = hv.x + hv.y + hv.z + hv.w;
    unsigned suf = tot;
    #pragma unroll
    for (int d = 1; d < 32; d <<= 1) {
        unsigned v = __shfl_down_sync(FULLM, suf, d);
        if (lane + d < 32) suf += v;
    }
    if (lane == 0) wsum[wid] = suf;
    __syncthreads();
    if (tid < 32) {
        unsigned v  = wsum[tid];
        unsigned sv = v;
        #pragma unroll
        for (int d = 1; d < 32; d <<= 1) {
            unsigned u = __shfl_down_sync(FULLM, sv, d);
            if (tid + d < 32) sv += u;
        }
        wsum[tid] = sv - v;    // exclusive suffix over warps > tid
    }
    __syncthreads();
    {
        unsigned run = wsum[wid] + (suf - tot);   // count in buckets above 4tid+3
        unsigned e3 = run;
        unsigned e2 = e3 + hv.w;
        unsigned e1 = e2 + hv.z;
        unsigned e0 = e1 + hv.y;
        uint4 ev = make_uint4(e0, e1, e2, e3);
        ((uint4*)hist)[tid]   = ev;   // hist now = running write cursor per bucket
        ((uint4*)bstart)[tid] = ev;   // immutable copy = segment start
        if      (e3 + hv.w >= (unsigned)KTOP) atomicMax(&sb, 4 * tid + 3);
        else if (e2 + hv.z >= (unsigned)KTOP) atomicMax(&sb, 4 * tid + 2);
        else if (e1 + hv.y >= (unsigned)KTOP) atomicMax(&sb, 4 * tid + 1);
        else if (e0 + hv.x >= (unsigned)KTOP) atomicMax(&sb, 4 * tid + 0);
    }
    // zero keys2 while waiting (no dependency on scan results)
    for (int i = tid; i < CAP; i += NTHR) keys2[i] = 0ull;
    __syncthreads();
    const int cutoff = sb;

    // ---- phase 3: bucket-scatter selection ----
    for (int i = tid; i < NV4; i += NTHR) {
        float4 v = conf4[i];
        int a = 4 * i;
        float sv[4] = {v.x, v.y, v.z, v.w};
        #pragma unroll
        for (int c = 0; c < 4; c++) {
            float s = sv[c];
            if (s > CONF_T) {
                int b = bucket_of(s);
                if (b >= cutoff) {
                    unsigned pos = atomicAdd(&hist[b], 1u);
                    if (pos < CAP)
                        keys[pos] = ((unsigned long long)ordkey(s) << 16)
                                  | (unsigned)(65535 - (a + c));
                }
            }
        }
    }
    __syncthreads();

    // ---- phase 4: exact within-bucket ranking -> keys2 globally sorted ----
    const int ntot = min((int)hist[cutoff], CAP);   // total selected
    for (int p = tid; p < ntot; p += NTHR) {
        unsigned long long key = keys[p];
        float sc = inv_ordkey((unsigned)(key >> 16));
        int b  = bucket_of(sc);
        int st = (int)bstart[b];
        int en = min((int)hist[b], CAP);
        int rank = st;
        for (int q = st; q < en; q++) rank += (keys[q] > key) ? 1 : 0;
        keys2[rank] = key;
    }
    __syncthreads();

    // ---- phase 5: decode + box gather ----
    for (int r = tid; r < KTOP; r += NTHR) {
        unsigned long long key = keys2[r];
        unsigned u = (unsigned)(key >> 16);
        int   anchor = 0;
        float sc     = -2.0f;
        if (u != 0u) {
            anchor = 65535 - (int)(key & 0xFFFFull);
            sc = inv_ordkey(u);
        }
        float cx = pimg[anchor];
        float cy = pimg[(size_t)NANCH + anchor];
        float w  = pimg[2 * (size_t)NANCH + anchor];
        float ht = pimg[3 * (size_t)NANCH + anchor];
        float hw = w * 0.5f, hh = ht * 0.5f;
        float4 b;
        b.x = fminf(fmaxf(cx - hw, 0.0f), IMGW);
        b.y = fminf(fmaxf(cy - hh, 0.0f), IMGW);
        b.z = fminf(fmaxf(cx + hw, 0.0f), IMGW);
        b.w = fminf(fmaxf(cy + hh, 0.0f), IMGW);
        sbox[r]   = b;
        sarea[r]  = __fmul_rn(b.z - b.x, b.w - b.y);
        sorder[r] = anchor;
        sscore[r] = sc;
    }
    if (tid < 32) ssup[tid] = 0;
    __syncthreads();

    // ---- phase 6: greedy NMS, tile-vs-kept-list ----
    const int irow = wid;
    const int jcol = lane;
    for (int base = 0; base < KTOP; base += 32) {
        int cj  = base + jcol;
        int cjc = min(cj, KTOP - 1);
        bool aj_valid = (cj < KTOP) && (sscore[cjc] > CONF_T);
        float4 bj = sbox[cjc];
        float  aj = sarea[cjc];

        bool sup = false;
        if (aj_valid) {
            const int cnt = s_count;
            for (int l = irow; l < cnt; l += 32) {   // no break: pipelined loads
                float4 bl = lbox[l];
                sup |= sup_test(bl.x, bl.y, bl.z, bl.w, larea[l],
                                bj.x, bj.y, bj.z, bj.w, aj);
            }
        }
        bool pair = false;
        if (irow < jcol) {
            float4 bi = sbox[base + irow];
            float  ai = sarea[base + irow];
            pair = sup_test(bi.x, bi.y, bi.z, bi.w, ai,
                            bj.x, bj.y, bj.z, bj.w, aj);
        }
        unsigned rowm = __ballot_sync(FULLM, pair);
        if (jcol == 0) srow[irow] = rowm;
        if (sup) ssup[jcol] = 1;
        __syncthreads();

        if (tid < 32) {
            int  c2  = base + lane;
            bool alive = (c2 < KTOP) && (sscore[min(c2, KTOP - 1)] > CONF_T) && (ssup[lane] == 0);
            unsigned initb = __ballot_sync(FULLM, alive);
            unsigned rm    = srow[lane];
            unsigned kept;
            if (__ballot_sync(FULLM, (rm & initb) != 0) == 0u) {
                kept = initb;
            } else {
                unsigned S = 0; kept = 0;
                #pragma unroll 4
                for (int ii = 0; ii < 32; ii++) {
                    unsigned ri = __shfl_sync(FULLM, rm, ii);
                    bool ki = ((initb >> ii) & 1u) && !((S >> ii) & 1u);
                    if (ki) { kept |= (1u << ii); S |= ri; }
                }
            }
            int nk  = __popc(kept);
            int old = s_count;
            if ((kept >> lane) & 1u) {
                int pos = old + __popc(kept & ((1u << lane) - 1u));
                lbox[pos]  = sbox[c2];
                larea[pos] = sarea[c2];
                if (pos < MAXDET) slist[pos] = c2;
            }
            ssup[lane] = 0;
            if (lane == 0) {
                s_count = old + nk;
                if (old + nk >= MAXDET) s_stop = 1;
            }
        }
        __syncthreads();
        if (s_stop) break;
    }
    __syncthreads();

    // ---- phase 7: write outputs ----
    const int cnt = min(s_count, MAXDET);
    const int OB  = 0;
    const int OSC = BS * MAXDET * 4;
    const int OKP = OSC + BS * MAXDET;
    for (int s = tid; s < MAXDET * 56; s += NTHR) {
        int r = s / 56, f = s % 56;
        int q = (r < cnt) ? slist[r] : -1;
        float v = 0.0f;
        if (q >= 0) {
            if (f < 4) {
                float4 b = sbox[q];
                v = (f == 0) ? b.x : (f == 1) ? b.y : (f == 2) ? b.z : b.w;
            } else if (f == 4) {
                v = sscore[q];
            } else {
                int c = f - 5;
                int a = sorder[q];
                v = pimg[(size_t)(5 + c) * NANCH + a];
                if (c < 2) v = fminf(fmaxf(v, 0.0f), IMGW);
            }
        }
        if (f < 4)       out[OB  + (img * MAXDET + r) * 4 + f] = v;
        else if (f == 4) out[OSC +  img * MAXDET + r] = v;
        else             out[OKP + (img * MAXDET + r) * 51 + (f - 5)] = v;
    }
}

// ---------------- launch ----------------
extern "C" void kernel_launch(void* const* d_in, const int* in_sizes, int n_in,
                              void* d_out, int out_size) {
    const float* preds = (const float*)d_in[0];
    float* out = (float*)d_out;
    cudaFuncSetAttribute(k_fused, cudaFuncAttributeMaxDynamicSharedMemorySize, SMEM_TOTAL);
    k_fused<<<BS, NTHR, SMEM_TOTAL>>>(preds, out);
}

// round 7
// speedup vs baseline: 5.2383x; 1.0518x over previous
#include <cuda_runtime.h>

#define BS      16
#define NANCH   33600
#define NV4     8400
#define NCH     56
#define KTOP    3000
#define CAP     4096
#define NB      4096
#define MAXDET  300
#define CONF_T  0.25f
#define IOU_T   0.7f
#define IMGW    1280.0f
#define FULLM   0xFFFFFFFFu
#define BPI     8
#define CHUNK   1050   // NV4 / BPI

// ---------------- global scratch (L2-resident) ----------------
__device__ unsigned           g_hist  [BS * NB];   // zeroed at end of k_main each run
__device__ unsigned           g_bstart[BS * NB];   // fully overwritten by k_scan
__device__ unsigned           g_cursor[BS * NB];   // fully overwritten by k_scan
__device__ int                g_cutoff[BS];
__device__ unsigned long long g_keys  [BS * CAP];  // only [bstart,cursor) slots read

__device__ __forceinline__ unsigned ordkey(float f) {
    unsigned b = __float_as_uint(f);
    return (b & 0x80000000u) ? ~b : (b | 0x80000000u);
}
__device__ __forceinline__ float inv_ordkey(unsigned u) {
    unsigned bits = (u & 0x80000000u) ? (u & 0x7FFFFFFFu) : ~u;
    return __uint_as_float(bits);
}
__device__ __forceinline__ int bucket_of(float s) {
    int b = (int)(s * 4096.0f);
    return min(4095, max(0, b));
}
// suppression test, bit-identical to reference rounding (rel_err=0 R1..R5)
__device__ __forceinline__ bool sup_test(float ax, float ay, float az, float aw, float aa,
                                         float bx, float by, float bz, float bw, float ab) {
    float xx1 = fmaxf(ax, bx);
    float yy1 = fmaxf(ay, by);
    float xx2 = fminf(az, bz);
    float yy2 = fminf(aw, bw);
    float ww  = fmaxf(xx2 - xx1, 0.0f);
    float hh  = fmaxf(yy2 - yy1, 0.0f);
    float inter = __fmul_rn(ww, hh);
    if (inter <= 0.0f) return false;
    float denom = __fadd_rn(__fsub_rn(__fadd_rn(aa, ab), inter), 1e-9f);
    return (inter / denom) > IOU_T;
}

// ---------------- K1: wide histogram (8 blocks / image) ----------------
__global__ void __launch_bounds__(1024) k_hist(const float* __restrict__ preds) {
    const int img  = blockIdx.x >> 3;
    const int part = blockIdx.x & 7;
    const float4* conf4 = (const float4*)(preds + (size_t)img * NCH * NANCH + 4 * (size_t)NANCH);
    unsigned* hist = g_hist + img * NB;
    const int st = part * CHUNK;
    const int en = min(NV4, st + CHUNK);
    for (int i = st + threadIdx.x; i < en; i += 1024) {
        float4 v = conf4[i];
        if (v.x > CONF_T) atomicAdd(&hist[bucket_of(v.x)], 1u);
        if (v.y > CONF_T) atomicAdd(&hist[bucket_of(v.y)], 1u);
        if (v.z > CONF_T) atomicAdd(&hist[bucket_of(v.z)], 1u);
        if (v.w > CONF_T) atomicAdd(&hist[bucket_of(v.w)], 1u);
    }
}

// ---------------- K2: suffix scan -> bucket starts + cutoff ----------------
__global__ void __launch_bounds__(1024) k_scan() {
    __shared__ unsigned wsum[32];
    __shared__ int sb;
    const int img  = blockIdx.x;
    const int tid  = threadIdx.x;
    const int lane = tid & 31;
    const int wid  = tid >> 5;
    if (tid == 0) sb = 0;
    __syncthreads();

    uint4 hv = ((const uint4*)(g_hist + img * NB))[tid];
    unsigned tot = hv.x + hv.y + hv.z + hv.w;
    unsigned suf = tot;
    #pragma unroll
    for (int d = 1; d < 32; d <<= 1) {
        unsigned v = __shfl_down_sync(FULLM, suf, d);
        if (lane + d < 32) suf += v;
    }
    if (lane == 0) wsum[wid] = suf;
    __syncthreads();
    if (tid < 32) {
        unsigned v  = wsum[tid];
        unsigned sv = v;
        #pragma unroll
        for (int d = 1; d < 32; d <<= 1) {
            unsigned u = __shfl_down_sync(FULLM, sv, d);
            if (tid + d < 32) sv += u;
        }
        wsum[tid] = sv - v;
    }
    __syncthreads();
    unsigned run = wsum[wid] + (suf - tot);
    unsigned e3 = run;
    unsigned e2 = e3 + hv.w;
    unsigned e1 = e2 + hv.z;
    unsigned e0 = e1 + hv.y;
    uint4 ev = make_uint4(e0, e1, e2, e3);
    ((uint4*)(g_bstart + img * NB))[tid] = ev;
    ((uint4*)(g_cursor + img * NB))[tid] = ev;
    if      (e3 + hv.w >= (unsigned)KTOP) atomicMax(&sb, 4 * tid + 3);
    else if (e2 + hv.z >= (unsigned)KTOP) atomicMax(&sb, 4 * tid + 2);
    else if (e1 + hv.y >= (unsigned)KTOP) atomicMax(&sb, 4 * tid + 1);
    else if (e0 + hv.x >= (unsigned)KTOP) atomicMax(&sb, 4 * tid + 0);
    __syncthreads();
    if (tid == 0) g_cutoff[img] = sb;
}

// ---------------- K3: wide bucket-scatter selection ----------------
__global__ void __launch_bounds__(1024) k_scatter(const float* __restrict__ preds) {
    const int img  = blockIdx.x >> 3;
    const int part = blockIdx.x & 7;
    const int cutoff = g_cutoff[img];
    const float4* conf4 = (const float4*)(preds + (size_t)img * NCH * NANCH + 4 * (size_t)NANCH);
    unsigned* cursor = g_cursor + img * NB;
    unsigned long long* keys = g_keys + img * CAP;
    const int st = part * CHUNK;
    const int en = min(NV4, st + CHUNK);
    for (int i = st + threadIdx.x; i < en; i += 1024) {
        float4 v = conf4[i];
        float sv[4] = {v.x, v.y, v.z, v.w};
        int a = 4 * i;
        #pragma unroll
        for (int c = 0; c < 4; c++) {
            float s = sv[c];
            if (s > CONF_T) {
                int b = bucket_of(s);
                if (b >= cutoff) {
                    unsigned pos = atomicAdd(&cursor[b], 1u);
                    if (pos < CAP)
                        keys[pos] = ((unsigned long long)ordkey(s) << 16)
                                  | (unsigned)(65535 - (a + c));
                }
            }
        }
    }
}

// ---------------- K4: rank + lazy-decode NMS + output ----------------
// smem layout (bytes)
#define OFF_EN     0                     // 4096*4
#define OFF_BST    16384                 // 4096*4
#define OFF_KEYS   32768                 // 4096*8
#define OFF_KEYS2  65536                 // 4096*8
#define OFF_LBOX   98304                 // 336*16
#define OFF_LAREA  (OFF_LBOX  + 5376)    // 336*4
#define OFF_SLIST  (OFF_LAREA + 1344)    // 336*4
#define OFF_TBOX   (OFF_SLIST + 1344)    // 2*32*16
#define OFF_TAREA  (OFF_TBOX  + 1024)    // 2*32*4
#define OFF_SROW   (OFF_TAREA + 256)     // 32*4
#define OFF_SSUP   (OFF_SROW  + 128)     // 32
#define SMEM_TOTAL (OFF_SSUP  + 64)

__global__ void __launch_bounds__(1024) k_main(const float* __restrict__ preds,
                                               float* __restrict__ out) {
    extern __shared__ char sm[];
    unsigned*           sen   = (unsigned*)(sm + OFF_EN);     // bucket END offsets
    unsigned*           sbst  = (unsigned*)(sm + OFF_BST);    // bucket START offsets
    unsigned long long* keys  = (unsigned long long*)(sm + OFF_KEYS);
    unsigned long long* keys2 = (unsigned long long*)(sm + OFF_KEYS2);
    float4*             lbox  = (float4*)(sm + OFF_LBOX);
    float*              larea = (float*)(sm + OFF_LAREA);
    int*                slist = (int*)(sm + OFF_SLIST);
    float4*             tbox  = (float4*)(sm + OFF_TBOX);    // [2][32]
    float*              tarea = (float*)(sm + OFF_TAREA);    // [2][32]
    unsigned*           srow  = (unsigned*)(sm + OFF_SROW);
    unsigned char*      ssup  = (unsigned char*)(sm + OFF_SSUP);
    __shared__ int s_count, s_stop;

    const int img  = blockIdx.x;
    const int tid  = threadIdx.x;
    const int lane = tid & 31;
    const int wid  = tid >> 5;
    const float* pimg = preds + (size_t)img * NCH * NANCH;

    // ---- load cursor-ends/bstart/keys from global (L2) ----
    // FIX (R6 bug): segment ends come from g_cursor (post-scatter write cursors),
    // NOT g_hist (raw counts). R5's in-place hist mutation made these the same array.
    ((uint4*)sen)[tid]  = ((const uint4*)(g_cursor + img * NB))[tid];
    ((uint4*)sbst)[tid] = ((const uint4*)(g_bstart + img * NB))[tid];
    for (int r = tid; r < CAP; r += 1024) {
        keys[r]  = g_keys[img * CAP + r];
        keys2[r] = 0ull;
    }
    if (tid == 0) { s_count = 0; s_stop = 0; }
    if (tid < 32) ssup[tid] = 0;
    __syncthreads();

    // zero g_hist for the next graph replay (independent of everything below)
    for (int i = tid; i < NB; i += 1024) g_hist[img * NB + i] = 0u;

    const int cutoff = g_cutoff[img];
    const int ntot   = min((int)sen[cutoff], CAP);   // total selected

    // ---- exact within-bucket ranking -> keys2 globally sorted desc ----
    for (int p = tid; p < ntot; p += 1024) {
        unsigned long long key = keys[p];
        float sc = inv_ordkey((unsigned)(key >> 16));
        int b  = bucket_of(sc);
        int st = (int)sbst[b];
        int en = min((int)sen[b], CAP);
        int rank = st;
        for (int q = st; q < en; q++) rank += (keys[q] > key) ? 1 : 0;
        keys2[rank] = key;
    }
    __syncthreads();

    // ---- preload tile 0 boxes (warp 0) ----
    if (wid == 0) {
        unsigned long long k0 = keys2[lane];
        int anchor = 65535 - (int)(k0 & 0xFFFFull);
        anchor = min(anchor, NANCH - 1);
        float cx = pimg[anchor];
        float cy = pimg[(size_t)NANCH + anchor];
        float w  = pimg[2 * (size_t)NANCH + anchor];
        float ht = pimg[3 * (size_t)NANCH + anchor];
        float hw = w * 0.5f, hh = ht * 0.5f;
        float4 b;
        b.x = fminf(fmaxf(cx - hw, 0.0f), IMGW);
        b.y = fminf(fmaxf(cy - hh, 0.0f), IMGW);
        b.z = fminf(fmaxf(cx + hw, 0.0f), IMGW);
        b.w = fminf(fmaxf(cy + hh, 0.0f), IMGW);
        tbox[lane]  = b;
        tarea[lane] = __fmul_rn(b.z - b.x, b.w - b.y);
    }
    __syncthreads();

    // ---- greedy NMS: tile-vs-kept-list, lazy double-buffered decode ----
    for (int base = 0; base < KTOP; base += 32) {
        const int buf = (base >> 5) & 1;
        // warp 1 prefetches raw data for tile base+32 (loads overlap phase A/B)
        float pcx = 0.f, pcy = 0.f, pwd = 0.f, pht = 0.f;
        const bool pnext = (wid == 1) && (base + 32 < KTOP);
        if (pnext) {
            unsigned long long kn = keys2[base + 32 + lane];
            int anchor = 65535 - (int)(kn & 0xFFFFull);
            anchor = min(anchor, NANCH - 1);
            pcx = pimg[anchor];
            pcy = pimg[(size_t)NANCH + anchor];
            pwd = pimg[2 * (size_t)NANCH + anchor];
            pht = pimg[3 * (size_t)NANCH + anchor];
        }

        // phase A: leader tests + intra-tile pair test
        const int cj = base + lane;
        float sc_j = inv_ordkey((unsigned)(keys2[min(cj, CAP - 1)] >> 16));
        bool ajv = (cj < KTOP) && (sc_j > CONF_T);   // zero key -> NaN -> false
        float4 bj = tbox[buf * 32 + lane];
        float  aj = tarea[buf * 32 + lane];

        bool sup = false;
        if (ajv) {
            const int cnt = s_count;
            for (int l = wid; l < cnt; l += 32) {
                float4 bl = lbox[l];
                sup |= sup_test(bl.x, bl.y, bl.z, bl.w, larea[l],
                                bj.x, bj.y, bj.z, bj.w, aj);
            }
        }
        bool pair = false;
        if (wid < lane) {
            float4 bi = tbox[buf * 32 + wid];
            float  ai = tarea[buf * 32 + wid];
            pair = sup_test(bi.x, bi.y, bi.z, bi.w, ai,
                            bj.x, bj.y, bj.z, bj.w, aj);
        }
        unsigned rowm = __ballot_sync(FULLM, pair);
        if (lane == 0) srow[wid] = rowm;
        if (sup) ssup[lane] = 1;
        __syncthreads();

        // phase B (warp 0): resolve intra-tile greedy + append leaders
        if (tid < 32) {
            int  c2 = base + lane;
            float sc2 = inv_ordkey((unsigned)(keys2[min(c2, CAP - 1)] >> 16));
            bool alive = (c2 < KTOP) && (sc2 > CONF_T) && (ssup[lane] == 0);
            unsigned initb = __ballot_sync(FULLM, alive);
            unsigned rm    = srow[lane];
            unsigned kept;
            if (__ballot_sync(FULLM, (rm & initb) != 0) == 0u) {
                kept = initb;
            } else {
                unsigned S = 0; kept = 0;
                #pragma unroll 4
                for (int ii = 0; ii < 32; ii++) {
                    unsigned ri = __shfl_sync(FULLM, rm, ii);
                    bool ki = ((initb >> ii) & 1u) && !((S >> ii) & 1u);
                    if (ki) { kept |= (1u << ii); S |= ri; }
                }
            }
            int nk  = __popc(kept);
            int old = s_count;
            if ((kept >> lane) & 1u) {
                int pos = old + __popc(kept & ((1u << lane) - 1u));
                lbox[pos]  = tbox[buf * 32 + lane];
                larea[pos] = tarea[buf * 32 + lane];
                if (pos < MAXDET) slist[pos] = c2;
            }
            ssup[lane] = 0;
            if (lane == 0) {
                s_count = old + nk;
                if (old + nk >= MAXDET) s_stop = 1;
            }
        }
        // warp 1: finish decode of next tile into the other buffer
        if (pnext) {
            float hw = pwd * 0.5f, hh = pht * 0.5f;
            float4 b;
            b.x = fminf(fmaxf(pcx - hw, 0.0f), IMGW);
            b.y = fminf(fmaxf(pcy - hh, 0.0f), IMGW);
            b.z = fminf(fmaxf(pcx + hw, 0.0f), IMGW);
            b.w = fminf(fmaxf(pcy + hh, 0.0f), IMGW);
            tbox[(buf ^ 1) * 32 + lane]  = b;
            tarea[(buf ^ 1) * 32 + lane] = __fmul_rn(b.z - b.x, b.w - b.y);
        }
        __syncthreads();
        if (s_stop) break;
    }
    __syncthreads();

    // ---- output: boxes from lbox, score/anchor from keys2, kpt gather ----
    const int cnt = min(s_count, MAXDET);
    const int OB  = 0;
    const int OSC = BS * MAXDET * 4;
    const int OKP = OSC + BS * MAXDET;
    for (int s = tid; s < MAXDET * 56; s += 1024) {
        int r = s / 56, f = s % 56;
        float v = 0.0f;
        if (r < cnt) {
            if (f < 4) {
                float4 b = lbox[r];
                v = (f == 0) ? b.x : (f == 1) ? b.y : (f == 2) ? b.z : b.w;
            } else {
                unsigned long long key = keys2[slist[r]];
                if (f == 4) {
                    v = inv_ordkey((unsigned)(key >> 16));
                } else {
                    int c = f - 5;
                    int a = 65535 - (int)(key & 0xFFFFull);
                    v = pimg[(size_t)(5 + c) * NANCH + a];
                    if (c < 2) v = fminf(fmaxf(v, 0.0f), IMGW);
                }
            }
        }
        if (f < 4)       out[OB  + (img * MAXDET + r) * 4 + f] = v;
        else if (f == 4) out[OSC +  img * MAXDET + r] = v;
        else             out[OKP + (img * MAXDET + r) * 51 + (f - 5)] = v;
    }
}

// ---------------- launch ----------------
extern "C" void kernel_launch(void* const* d_in, const int* in_sizes, int n_in,
                              void* d_out, int out_size) {
    const float* preds = (const float*)d_in[0];
    float* out = (float*)d_out;
    cudaFuncSetAttribute(k_main, cudaFuncAttributeMaxDynamicSharedMemorySize, SMEM_TOTAL);
    k_hist   <<<BS * BPI, 1024>>>(preds);
    k_scan   <<<BS,       1024>>>();
    k_scatter<<<BS * BPI, 1024>>>(preds);
    k_main   <<<BS, 1024, SMEM_TOTAL>>>(preds, out);
}

// round 8
// speedup vs baseline: 6.2407x; 1.1914x over previous
#include <cuda_runtime.h>

#define BS      16
#define NANCH   33600
#define NV4     8400
#define NCH     56
#define KTOP    3000
#define CAP     4096
#define NB      4096
#define MAXDET  300
#define CONF_T  0.25f
#define IOU_T   0.7f
#define IMGW    1280.0f
#define FULLM   0xFFFFFFFFu
#define BPI     8
#define CHUNK   1050   // NV4 / BPI

// ---------------- global scratch (L2-resident) ----------------
__device__ unsigned           g_hist  [BS * NB];    // zeroed by k_main each run
__device__ unsigned           g_bstart[BS * NB];    // fully overwritten by k_scan
__device__ unsigned           g_cursor[BS * NB];    // fully overwritten by k_scan
__device__ int                g_cutoff[BS];
__device__ unsigned long long g_keys  [BS * CAP];   // only [bstart,cursor) slots read
__device__ int                g_cnt   [BS];
__device__ float4             g_selbox  [BS * MAXDET];
__device__ float              g_selscore[BS * MAXDET];
__device__ int                g_selanch [BS * MAXDET];

__device__ __forceinline__ unsigned ordkey(float f) {
    unsigned b = __float_as_uint(f);
    return (b & 0x80000000u) ? ~b : (b | 0x80000000u);
}
__device__ __forceinline__ float inv_ordkey(unsigned u) {
    unsigned bits = (u & 0x80000000u) ? (u & 0x7FFFFFFFu) : ~u;
    return __uint_as_float(bits);
}
__device__ __forceinline__ int bucket_of(float s) {
    int b = (int)(s * 4096.0f);
    return min(4095, max(0, b));
}
// suppression test, bit-identical to reference rounding (rel_err=0 R1..R7)
__device__ __forceinline__ bool sup_test(float ax, float ay, float az, float aw, float aa,
                                         float bx, float by, float bz, float bw, float ab) {
    float xx1 = fmaxf(ax, bx);
    float yy1 = fmaxf(ay, by);
    float xx2 = fminf(az, bz);
    float yy2 = fminf(aw, bw);
    float ww  = fmaxf(xx2 - xx1, 0.0f);
    float hh  = fmaxf(yy2 - yy1, 0.0f);
    float inter = __fmul_rn(ww, hh);
    if (inter <= 0.0f) return false;
    float denom = __fadd_rn(__fsub_rn(__fadd_rn(aa, ab), inter), 1e-9f);
    return (inter / denom) > IOU_T;
}

// ---------------- K1: wide histogram ----------------
__global__ void __launch_bounds__(1024) k_hist(const float* __restrict__ preds) {
    const int img  = blockIdx.x >> 3;
    const int part = blockIdx.x & 7;
    const float4* conf4 = (const float4*)(preds + (size_t)img * NCH * NANCH + 4 * (size_t)NANCH);
    unsigned* hist = g_hist + img * NB;
    const int st = part * CHUNK;
    const int en = min(NV4, st + CHUNK);
    for (int i = st + threadIdx.x; i < en; i += 1024) {
        float4 v = conf4[i];
        if (v.x > CONF_T) atomicAdd(&hist[bucket_of(v.x)], 1u);
        if (v.y > CONF_T) atomicAdd(&hist[bucket_of(v.y)], 1u);
        if (v.z > CONF_T) atomicAdd(&hist[bucket_of(v.z)], 1u);
        if (v.w > CONF_T) atomicAdd(&hist[bucket_of(v.w)], 1u);
    }
}

// ---------------- K2: suffix scan -> bucket starts + cutoff ----------------
__global__ void __launch_bounds__(1024) k_scan() {
    __shared__ unsigned wsum[32];
    __shared__ int sb;
    const int img  = blockIdx.x;
    const int tid  = threadIdx.x;
    const int lane = tid & 31;
    const int wid  = tid >> 5;
    if (tid == 0) sb = 0;
    __syncthreads();

    uint4 hv = ((const uint4*)(g_hist + img * NB))[tid];
    unsigned tot = hv.x + hv.y + hv.z + hv.w;
    unsigned suf = tot;
    #pragma unroll
    for (int d = 1; d < 32; d <<= 1) {
        unsigned v = __shfl_down_sync(FULLM, suf, d);
        if (lane + d < 32) suf += v;
    }
    if (lane == 0) wsum[wid] = suf;
    __syncthreads();
    if (tid < 32) {
        unsigned v  = wsum[tid];
        unsigned sv = v;
        #pragma unroll
        for (int d = 1; d < 32; d <<= 1) {
            unsigned u = __shfl_down_sync(FULLM, sv, d);
            if (tid + d < 32) sv += u;
        }
        wsum[tid] = sv - v;
    }
    __syncthreads();
    unsigned run = wsum[wid] + (suf - tot);
    unsigned e3 = run;
    unsigned e2 = e3 + hv.w;
    unsigned e1 = e2 + hv.z;
    unsigned e0 = e1 + hv.y;
    uint4 ev = make_uint4(e0, e1, e2, e3);
    ((uint4*)(g_bstart + img * NB))[tid] = ev;
    ((uint4*)(g_cursor + img * NB))[tid] = ev;
    if      (e3 + hv.w >= (unsigned)KTOP) atomicMax(&sb, 4 * tid + 3);
    else if (e2 + hv.z >= (unsigned)KTOP) atomicMax(&sb, 4 * tid + 2);
    else if (e1 + hv.y >= (unsigned)KTOP) atomicMax(&sb, 4 * tid + 1);
    else if (e0 + hv.x >= (unsigned)KTOP) atomicMax(&sb, 4 * tid + 0);
    __syncthreads();
    if (tid == 0) g_cutoff[img] = sb;
}

// ---------------- K3: wide bucket-scatter selection ----------------
__global__ void __launch_bounds__(1024) k_scatter(const float* __restrict__ preds) {
    const int img  = blockIdx.x >> 3;
    const int part = blockIdx.x & 7;
    const int cutoff = g_cutoff[img];
    const float4* conf4 = (const float4*)(preds + (size_t)img * NCH * NANCH + 4 * (size_t)NANCH);
    unsigned* cursor = g_cursor + img * NB;
    unsigned long long* keys = g_keys + img * CAP;
    const int st = part * CHUNK;
    const int en = min(NV4, st + CHUNK);
    for (int i = st + threadIdx.x; i < en; i += 1024) {
        float4 v = conf4[i];
        float sv[4] = {v.x, v.y, v.z, v.w};
        int a = 4 * i;
        #pragma unroll
        for (int c = 0; c < 4; c++) {
            float s = sv[c];
            if (s > CONF_T) {
                int b = bucket_of(s);
                if (b >= cutoff) {
                    unsigned pos = atomicAdd(&cursor[b], 1u);
                    if (pos < CAP)
                        keys[pos] = ((unsigned long long)ordkey(s) << 16)
                                  | (unsigned)(65535 - (a + c));
                }
            }
        }
    }
}

// ---------------- K4: rank + lazy-decode NMS (no output) ----------------
// smem layout (bytes)
#define OFF_EN     0                     // 4096*4
#define OFF_BST    16384                 // 4096*4
#define OFF_KEYS   32768                 // 4096*8
#define OFF_KEYS2  65536                 // 4096*8
#define OFF_LBOX   98304                 // 336*16
#define OFF_LAREA  (OFF_LBOX  + 5376)
#define OFF_SLIST  (OFF_LAREA + 1344)
#define OFF_TBOX   (OFF_SLIST + 1344)    // 2*32*16
#define OFF_TAREA  (OFF_TBOX  + 1024)    // 2*32*4
#define OFF_SROW   (OFF_TAREA + 256)     // 32*4
#define OFF_SSUP   (OFF_SROW  + 128)     // 32
#define SMEM_TOTAL (OFF_SSUP  + 64)

__global__ void __launch_bounds__(1024) k_main(const float* __restrict__ preds) {
    extern __shared__ char sm[];
    unsigned*           sen   = (unsigned*)(sm + OFF_EN);
    unsigned*           sbst  = (unsigned*)(sm + OFF_BST);
    unsigned long long* keys  = (unsigned long long*)(sm + OFF_KEYS);
    unsigned long long* keys2 = (unsigned long long*)(sm + OFF_KEYS2);
    float4*             lbox  = (float4*)(sm + OFF_LBOX);
    float*              larea = (float*)(sm + OFF_LAREA);
    int*                slist = (int*)(sm + OFF_SLIST);
    float4*             tbox  = (float4*)(sm + OFF_TBOX);
    float*              tarea = (float*)(sm + OFF_TAREA);
    unsigned*           srow  = (unsigned*)(sm + OFF_SROW);
    unsigned char*      ssup  = (unsigned char*)(sm + OFF_SSUP);
    __shared__ int s_count, s_stop;

    const int img  = blockIdx.x;
    const int tid  = threadIdx.x;
    const int lane = tid & 31;
    const int wid  = tid >> 5;
    const float* pimg = preds + (size_t)img * NCH * NANCH;

    ((uint4*)sen)[tid]  = ((const uint4*)(g_cursor + img * NB))[tid];
    ((uint4*)sbst)[tid] = ((const uint4*)(g_bstart + img * NB))[tid];
    for (int r = tid; r < CAP; r += 1024) {
        keys[r]  = g_keys[img * CAP + r];
        keys2[r] = 0ull;
    }
    if (tid == 0) { s_count = 0; s_stop = 0; }
    if (tid < 32) ssup[tid] = 0;
    __syncthreads();

    // zero g_hist for next graph replay
    for (int i = tid; i < NB; i += 1024) g_hist[img * NB + i] = 0u;

    const int cutoff = g_cutoff[img];
    const int ntot   = min((int)sen[cutoff], CAP);

    // ---- exact within-bucket ranking -> keys2 sorted desc ----
    for (int p = tid; p < ntot; p += 1024) {
        unsigned long long key = keys[p];
        float sc = inv_ordkey((unsigned)(key >> 16));
        int b  = bucket_of(sc);
        int st = (int)sbst[b];
        int en = min((int)sen[b], CAP);
        int rank = st;
        for (int q = st; q < en; q++) rank += (keys[q] > key) ? 1 : 0;
        keys2[rank] = key;
    }
    __syncthreads();

    // ---- preload tile 0 (warp 0) ----
    if (wid == 0) {
        unsigned long long k0 = keys2[lane];
        int anchor = 65535 - (int)(k0 & 0xFFFFull);
        anchor = min(anchor, NANCH - 1);
        float cx = pimg[anchor];
        float cy = pimg[(size_t)NANCH + anchor];
        float w  = pimg[2 * (size_t)NANCH + anchor];
        float ht = pimg[3 * (size_t)NANCH + anchor];
        float hw = w * 0.5f, hh = ht * 0.5f;
        float4 b;
        b.x = fminf(fmaxf(cx - hw, 0.0f), IMGW);
        b.y = fminf(fmaxf(cy - hh, 0.0f), IMGW);
        b.z = fminf(fmaxf(cx + hw, 0.0f), IMGW);
        b.w = fminf(fmaxf(cy + hh, 0.0f), IMGW);
        tbox[lane]  = b;
        tarea[lane] = __fmul_rn(b.z - b.x, b.w - b.y);
    }
    __syncthreads();

    // ---- greedy NMS: tile-vs-kept-list, lazy double-buffered decode ----
    for (int base = 0; base < KTOP; base += 32) {
        const int buf = (base >> 5) & 1;
        float pcx = 0.f, pcy = 0.f, pwd = 0.f, pht = 0.f;
        const bool pnext = (wid == 1) && (base + 32 < KTOP);
        if (pnext) {
            unsigned long long kn = keys2[base + 32 + lane];
            int anchor = 65535 - (int)(kn & 0xFFFFull);
            anchor = min(anchor, NANCH - 1);
            pcx = pimg[anchor];
            pcy = pimg[(size_t)NANCH + anchor];
            pwd = pimg[2 * (size_t)NANCH + anchor];
            pht = pimg[3 * (size_t)NANCH + anchor];
        }

        const int cj = base + lane;
        float sc_j = inv_ordkey((unsigned)(keys2[min(cj, CAP - 1)] >> 16));
        bool ajv = (cj < KTOP) && (sc_j > CONF_T);
        float4 bj = tbox[buf * 32 + lane];
        float  aj = tarea[buf * 32 + lane];

        bool sup = false;
        if (ajv) {
            const int cnt = s_count;
            for (int l = wid; l < cnt; l += 32) {
                float4 bl = lbox[l];
                sup |= sup_test(bl.x, bl.y, bl.z, bl.w, larea[l],
                                bj.x, bj.y, bj.z, bj.w, aj);
            }
        }
        bool pair = false;
        if (wid < lane) {
            float4 bi = tbox[buf * 32 + wid];
            float  ai = tarea[buf * 32 + wid];
            pair = sup_test(bi.x, bi.y, bi.z, bi.w, ai,
                            bj.x, bj.y, bj.z, bj.w, aj);
        }
        unsigned rowm = __ballot_sync(FULLM, pair);
        if (lane == 0) srow[wid] = rowm;
        if (sup) ssup[lane] = 1;
        __syncthreads();

        if (tid < 32) {
            int  c2 = base + lane;
            float sc2 = inv_ordkey((unsigned)(keys2[min(c2, CAP - 1)] >> 16));
            bool alive = (c2 < KTOP) && (sc2 > CONF_T) && (ssup[lane] == 0);
            unsigned initb = __ballot_sync(FULLM, alive);
            unsigned rm    = srow[lane];
            unsigned kept;
            if (__ballot_sync(FULLM, (rm & initb) != 0) == 0u) {
                kept = initb;
            } else {
                unsigned S = 0; kept = 0;
                #pragma unroll 4
                for (int ii = 0; ii < 32; ii++) {
                    unsigned ri = __shfl_sync(FULLM, rm, ii);
                    bool ki = ((initb >> ii) & 1u) && !((S >> ii) & 1u);
                    if (ki) { kept |= (1u << ii); S |= ri; }
                }
            }
            int nk  = __popc(kept);
            int old = s_count;
            if ((kept >> lane) & 1u) {
                int pos = old + __popc(kept & ((1u << lane) - 1u));
                lbox[pos]  = tbox[buf * 32 + lane];
                larea[pos] = tarea[buf * 32 + lane];
                if (pos < MAXDET) slist[pos] = c2;
            }
            ssup[lane] = 0;
            if (lane == 0) {
                s_count = old + nk;
                if (old + nk >= MAXDET) s_stop = 1;
            }
        }
        if (pnext) {
            float hw = pwd * 0.5f, hh = pht * 0.5f;
            float4 b;
            b.x = fminf(fmaxf(pcx - hw, 0.0f), IMGW);
            b.y = fminf(fmaxf(pcy - hh, 0.0f), IMGW);
            b.z = fminf(fmaxf(pcx + hw, 0.0f), IMGW);
            b.w = fminf(fmaxf(pcy + hh, 0.0f), IMGW);
            tbox[(buf ^ 1) * 32 + lane]  = b;
            tarea[(buf ^ 1) * 32 + lane] = __fmul_rn(b.z - b.x, b.w - b.y);
        }
        __syncthreads();
        if (s_stop) break;
    }
    __syncthreads();

    // ---- emit compact per-image selection ----
    const int cnt = min(s_count, MAXDET);
    if (tid < cnt) {
        unsigned long long key = keys2[slist[tid]];
        g_selbox  [img * MAXDET + tid] = lbox[tid];
        g_selscore[img * MAXDET + tid] = inv_ordkey((unsigned)(key >> 16));
        g_selanch [img * MAXDET + tid] = 65535 - (int)(key & 0xFFFFull);
    }
    if (tid == 0) g_cnt[img] = cnt;
}

// ---------------- K5: wide output writer ----------------
#define TOTOUT (BS * MAXDET * 56)
__global__ void __launch_bounds__(1024) k_out(const float* __restrict__ preds,
                                              float* __restrict__ out) {
    int s = blockIdx.x * 1024 + threadIdx.x;
    if (s >= TOTOUT) return;
    const int img = s / (MAXDET * 56);
    const int rem = s % (MAXDET * 56);
    const int r   = rem / 56;
    const int f   = rem % 56;
    const int cnt = g_cnt[img];

    float v = 0.0f;
    if (r < cnt) {
        if (f < 4) {
            float4 b = g_selbox[img * MAXDET + r];
            v = (f == 0) ? b.x : (f == 1) ? b.y : (f == 2) ? b.z : b.w;
        } else if (f == 4) {
            v = g_selscore[img * MAXDET + r];
        } else {
            int c = f - 5;
            int a = g_selanch[img * MAXDET + r];
            v = preds[(size_t)img * NCH * NANCH + (size_t)(5 + c) * NANCH + a];
            if (c < 2) v = fminf(fmaxf(v, 0.0f), IMGW);
        }
    }
    const int OSC = BS * MAXDET * 4;
    const int OKP = OSC + BS * MAXDET;
    if (f < 4)       out[(img * MAXDET + r) * 4 + f] = v;
    else if (f == 4) out[OSC + img * MAXDET + r] = v;
    else             out[OKP + (img * MAXDET + r) * 51 + (f - 5)] = v;
}

// ---------------- launch ----------------
extern "C" void kernel_launch(void* const* d_in, const int* in_sizes, int n_in,
                              void* d_out, int out_size) {
    const float* preds = (const float*)d_in[0];
    float* out = (float*)d_out;
    cudaFuncSetAttribute(k_main, cudaFuncAttributeMaxDynamicSharedMemorySize, SMEM_TOTAL);
    k_hist   <<<BS * BPI, 1024>>>(preds);
    k_scan   <<<BS,       1024>>>();
    k_scatter<<<BS * BPI, 1024>>>(preds);
    k_main   <<<BS, 1024, SMEM_TOTAL>>>(preds);
    k_out    <<<(TOTOUT + 1023) / 1024, 1024>>>(preds, out);
}